// round 6
// baseline (speedup 1.0000x reference)
#include <cuda_runtime.h>
#include <cuda_bf16.h>
#include <math.h>
#include <stdint.h>

#define B_   8
#define S_   4096
#define E_   512
#define H_   8
#define D_   64
#define M_   (B_ * S_)      // 32768 rows
#define EPS_ 1e-6f

// -------- scratch (device globals; no allocations allowed) --------
__device__ __align__(16) float g_q[(size_t)M_ * E_];
__device__ __align__(16) float g_k[(size_t)M_ * E_];
__device__ __align__(16) float g_v[(size_t)M_ * E_];
__device__ __align__(16) float g_kv[B_ * H_ * D_ * D_];           // [bh][m][d] (transposed)
__device__ __align__(16) float g_ksum[B_ * H_ * D_];
__device__ __align__(16) float g_kvp[(size_t)B_ * H_ * 32 * D_ * D_];  // [bh][ch][d][m]
__device__ __align__(16) float g_ksp[B_ * H_ * 4 * D_];
// bf16 split operands
__device__ __align__(16) __nv_bfloat16 g_xh[(size_t)M_ * E_];
__device__ __align__(16) __nv_bfloat16 g_xl[(size_t)M_ * E_];
__device__ __align__(16) __nv_bfloat16 g_ah[(size_t)M_ * E_];
__device__ __align__(16) __nv_bfloat16 g_al[(size_t)M_ * E_];
__device__ __align__(16) __nv_bfloat16 g_wh[4 * 512 * 512];  // transposed [n][k]
__device__ __align__(16) __nv_bfloat16 g_wl[4 * 512 * 512];

// ================= portable PTX helpers =================
static __device__ __forceinline__ uint32_t smem_u32(const void* p) {
    uint32_t a;
    asm("{ .reg .u64 t; cvta.to.shared.u64 t, %1; cvt.u32.u64 %0, t; }" : "=r"(a) : "l"(p));
    return a;
}
static __device__ __forceinline__ void ldsm4(uint32_t* r, uint32_t addr) {
    asm volatile("ldmatrix.sync.aligned.m8n8.x4.shared.b16 {%0,%1,%2,%3}, [%4];"
                 : "=r"(r[0]), "=r"(r[1]), "=r"(r[2]), "=r"(r[3]) : "r"(addr));
}
static __device__ __forceinline__ void mma16816(float* c, const uint32_t* a, const uint32_t* b) {
    asm volatile("mma.sync.aligned.m16n8k16.row.col.f32.bf16.bf16.f32 "
                 "{%0,%1,%2,%3}, {%4,%5,%6,%7}, {%8,%9}, {%0,%1,%2,%3};"
                 : "+f"(c[0]), "+f"(c[1]), "+f"(c[2]), "+f"(c[3])
                 : "r"(a[0]), "r"(a[1]), "r"(a[2]), "r"(a[3]), "r"(b[0]), "r"(b[1]));
}
static __device__ __forceinline__ void cp16(uint32_t dst, const void* src) {
    asm volatile("cp.async.cg.shared.global [%0], [%1], 16;" :: "r"(dst), "l"(src));
}
static __device__ __forceinline__ void cp_commit() {
    asm volatile("cp.async.commit_group;");
}
template <int N> static __device__ __forceinline__ void cp_wait() {
    asm volatile("cp.async.wait_group %0;" :: "n"(N));
}

// ============================================================
// HMMA bf16 3-split GEMM, 2-stage cp.async pipeline.
// C[m0:+128, n0:+64] = act(A @ B^T + bias). BK=64.
// 256 threads = 8 warps (4m x 2n), warp tile 32x32.
// Dynamic SMEM 96KB: 2 stages x (Ah 16K | Al 16K | Bh 8K | Bl 8K).
// ============================================================
#define STAGE_B 49152
#define GEMM_DSMEM (2 * STAGE_B)

static __device__ __forceinline__ void issue_stage(
    uint32_t sb, int tid, int k0, int m0, int n0,
    const char* Ahb, const char* Alb, const char* Bhb, const char* Blb)
{
#pragma unroll
    for (int i = 0; i < 4; i++) {
        int idx = i * 256 + tid;
        int r = idx >> 3, c = idx & 7;
        uint32_t so = (uint32_t)(r * 128 + ((c ^ (r & 7)) << 4));
        size_t go = ((size_t)(m0 + r) * 512 + k0) * 2 + c * 16;
        cp16(sb + so,         Ahb + go);
        cp16(sb + 16384 + so, Alb + go);
    }
#pragma unroll
    for (int i = 0; i < 2; i++) {
        int idx = i * 256 + tid;
        int r = idx >> 3, c = idx & 7;
        uint32_t so = (uint32_t)(r * 128 + ((c ^ (r & 7)) << 4));
        size_t go = ((size_t)(n0 + r) * 512 + k0) * 2 + c * 16;
        cp16(sb + 32768 + so, Bhb + go);
        cp16(sb + 40960 + so, Blb + go);
    }
    cp_commit();
}

static __device__ __forceinline__ void gemm_mma_body(
    const __nv_bfloat16* __restrict__ Ah, const __nv_bfloat16* __restrict__ Al,
    const __nv_bfloat16* __restrict__ Bh, const __nv_bfloat16* __restrict__ Bl,
    const float* __restrict__ bias, float* __restrict__ C,
    bool act, int m0, int n0)
{
    extern __shared__ __align__(1024) uint8_t dsm[];
    const int tid = threadIdx.x;
    const int wid = tid >> 5, lane = tid & 31;
    const int wm = wid & 3;
    const int wn = wid >> 2;
    const uint32_t sbase = smem_u32(dsm);

    float acc[2][4][4];
#pragma unroll
    for (int i = 0; i < 2; i++)
#pragma unroll
        for (int j = 0; j < 4; j++)
#pragma unroll
            for (int t = 0; t < 4; t++) acc[i][j][t] = 0.f;

    const int rA  = wm * 32 + (lane & 15);
    const int khA = (lane >> 4) & 1;
    const int rB  = wn * 32 + (lane & 7) + ((lane >> 1) & 8);
    const int khB = (lane >> 3) & 1;
    const int swA = rA & 7;
    const int swB = rB & 7;

    const char* Ahb = (const char*)Ah;
    const char* Alb = (const char*)Al;
    const char* Bhb = (const char*)Bh;
    const char* Blb = (const char*)Bl;

    issue_stage(sbase, tid, 0, m0, n0, Ahb, Alb, Bhb, Blb);

    for (int kb = 0; kb < 8; kb++) {
        if (kb < 7) {
            issue_stage(sbase + ((kb + 1) & 1) * STAGE_B, tid, (kb + 1) * 64,
                        m0, n0, Ahb, Alb, Bhb, Blb);
            cp_wait<1>();
        } else {
            cp_wait<0>();
        }
        __syncthreads();

        const uint32_t st = sbase + (kb & 1) * STAGE_B;
        const uint32_t sAh = st, sAl = st + 16384, sBh = st + 32768, sBl = st + 40960;

#pragma unroll
        for (int ks = 0; ks < 4; ks++) {
            uint32_t aH[8], aL[8], bH[8], bL[8];
            int cA = ks * 2 + khA;
            uint32_t aoff = (uint32_t)(rA * 128 + ((cA ^ swA) << 4));
            int cB = ks * 2 + khB;
            uint32_t boff = (uint32_t)(rB * 128 + ((cB ^ swB) << 4));

            ldsm4(aH + 0, sAh + aoff);
            ldsm4(aH + 4, sAh + aoff + 2048);
            ldsm4(bH + 0, sBh + boff);
            ldsm4(bH + 4, sBh + boff + 2048);
#pragma unroll
            for (int mt = 0; mt < 2; mt++)
#pragma unroll
                for (int nt = 0; nt < 4; nt++)
                    mma16816(acc[mt][nt], aH + 4 * mt, bH + nt * 2);

            ldsm4(aL + 0, sAl + aoff);
            ldsm4(aL + 4, sAl + aoff + 2048);
#pragma unroll
            for (int mt = 0; mt < 2; mt++)
#pragma unroll
                for (int nt = 0; nt < 4; nt++)
                    mma16816(acc[mt][nt], aL + 4 * mt, bH + nt * 2);

            ldsm4(bL + 0, sBl + boff);
            ldsm4(bL + 4, sBl + boff + 2048);
#pragma unroll
            for (int mt = 0; mt < 2; mt++)
#pragma unroll
                for (int nt = 0; nt < 4; nt++)
                    mma16816(acc[mt][nt], aH + 4 * mt, bL + nt * 2);
        }
        __syncthreads();
    }

    // --- epilogue ---
    const int g = lane >> 2, t4 = lane & 3;
#pragma unroll
    for (int mt = 0; mt < 2; mt++) {
#pragma unroll
        for (int nt = 0; nt < 4; nt++) {
            int row = m0 + wm * 32 + mt * 16 + g;
            int col = n0 + wn * 32 + nt * 8 + t4 * 2;
            float b0 = bias[col], b1 = bias[col + 1];
            float f0 = acc[mt][nt][0] + b0;
            float f1 = acc[mt][nt][1] + b1;
            float f2 = acc[mt][nt][2] + b0;
            float f3 = acc[mt][nt][3] + b1;
            if (act) {
                f0 = (f0 > 0.f) ? (f0 + 1.f) : __expf(f0);
                f1 = (f1 > 0.f) ? (f1 + 1.f) : __expf(f1);
                f2 = (f2 > 0.f) ? (f2 + 1.f) : __expf(f2);
                f3 = (f3 > 0.f) ? (f3 + 1.f) : __expf(f3);
            }
            *(float2*)(C + (size_t)row * 512 + col)       = make_float2(f0, f1);
            *(float2*)(C + (size_t)(row + 8) * 512 + col) = make_float2(f2, f3);
        }
    }
}

// grid (256, 8, 3): z = matrix (0=Q,1=K,2=V), y = n-tile of 64
__global__ __launch_bounds__(256, 2) void qkv_mma(const float* __restrict__ bq,
                                                  const float* __restrict__ bk,
                                                  const float* __restrict__ bv)
{
    int mat = blockIdx.z;
    const __nv_bfloat16* Bh = g_wh + (size_t)mat * 262144;
    const __nv_bfloat16* Bl = g_wl + (size_t)mat * 262144;
    const float* bias = (mat == 0) ? bq : (mat == 1) ? bk : bv;
    float* C = (mat == 0) ? g_q : (mat == 1) ? g_k : g_v;
    gemm_mma_body(g_xh, g_xl, Bh, Bl, bias, C, mat < 2,
                  blockIdx.x * 128, blockIdx.y * 64);
}

// grid (256, 8)
__global__ __launch_bounds__(256, 2) void out_mma(float* __restrict__ out,
                                                  const float* __restrict__ bo)
{
    gemm_mma_body(g_ah, g_al, g_wh + (size_t)3 * 262144, g_wl + (size_t)3 * 262144,
                  bo, out, false, blockIdx.x * 128, blockIdx.y * 64);
}

// ============================================================
// split x -> bf16 hi/lo
__global__ __launch_bounds__(256) void split_x(const float* __restrict__ x)
{
    size_t i4 = ((size_t)blockIdx.x * 256 + threadIdx.x) * 4;
    float4 v = *(const float4*)(x + i4);
    float vv[4] = {v.x, v.y, v.z, v.w};
    __nv_bfloat16 h[4], l[4];
#pragma unroll
    for (int j = 0; j < 4; j++) {
        h[j] = __float2bfloat16(vv[j]);
        l[j] = __float2bfloat16(vv[j] - __bfloat162float(h[j]));
    }
    *(__nv_bfloat162*)(g_xh + i4)     = __nv_bfloat162(h[0], h[1]);
    *(__nv_bfloat162*)(g_xh + i4 + 2) = __nv_bfloat162(h[2], h[3]);
    *(__nv_bfloat162*)(g_xl + i4)     = __nv_bfloat162(l[0], l[1]);
    *(__nv_bfloat162*)(g_xl + i4 + 2) = __nv_bfloat162(l[2], l[3]);
}

// transpose + split weights
__global__ __launch_bounds__(256) void tsplit_w(const float* __restrict__ Wq,
                                                const float* __restrict__ Wk,
                                                const float* __restrict__ Wv,
                                                const float* __restrict__ Wo)
{
    const float* W = (blockIdx.z == 0) ? Wq : (blockIdx.z == 1) ? Wk
                   : (blockIdx.z == 2) ? Wv : Wo;
    __nv_bfloat16* oh = g_wh + (size_t)blockIdx.z * 262144;
    __nv_bfloat16* ol = g_wl + (size_t)blockIdx.z * 262144;
    __shared__ float t[32][33];
    int nx = blockIdx.x * 32 + threadIdx.x;
    int k0 = blockIdx.y * 32;
#pragma unroll
    for (int j = 0; j < 4; j++)
        t[threadIdx.y + j * 8][threadIdx.x] = W[(size_t)(k0 + threadIdx.y + j * 8) * 512 + nx];
    __syncthreads();
#pragma unroll
    for (int j = 0; j < 4; j++) {
        int nr = blockIdx.x * 32 + threadIdx.y + j * 8;
        int kc = k0 + threadIdx.x;
        float v = t[threadIdx.x][threadIdx.y + j * 8];
        __nv_bfloat16 h = __float2bfloat16(v);
        oh[(size_t)nr * 512 + kc] = h;
        ol[(size_t)nr * 512 + kc] = __float2bfloat16(v - __bfloat162float(h));
    }
}

// ============================================================
// KV partials: register outer-product, no barriers.
// grid (8, 64) block 256. Thread: 16 d x 4 m tile over 128 rows.
// chunk = blockIdx.x*4 + (tid>>6)  -> 32 chunks of 128 rows.
__global__ __launch_bounds__(256) void kv_partial()
{
    const int bh = blockIdx.y;
    const int b = bh >> 3, h = bh & 7;
    const int tid = threadIdx.x;
    const int ch = blockIdx.x * 4 + (tid >> 6);
    const int t64 = tid & 63;
    const int dg = t64 >> 4;     // d base = dg*16
    const int mg = t64 & 15;     // m base = mg*4

    const size_t base = ((size_t)(b * S_ + ch * 128)) * 512 + h * 64;
    const float* kbase = g_k + base + dg * 16;
    const float* vbase = g_v + base + mg * 4;

    float4 acc[16];
#pragma unroll
    for (int j = 0; j < 16; j++) acc[j] = make_float4(0.f, 0.f, 0.f, 0.f);

#pragma unroll 2
    for (int s = 0; s < 128; s++) {
        const float4* kp = (const float4*)(kbase + (size_t)s * 512);
        float4 k0 = kp[0], k1 = kp[1], k2 = kp[2], k3 = kp[3];
        float4 vv = *(const float4*)(vbase + (size_t)s * 512);
        float kf[16] = {k0.x, k0.y, k0.z, k0.w, k1.x, k1.y, k1.z, k1.w,
                        k2.x, k2.y, k2.z, k2.w, k3.x, k3.y, k3.z, k3.w};
#pragma unroll
        for (int j = 0; j < 16; j++) {
            acc[j].x += kf[j] * vv.x;
            acc[j].y += kf[j] * vv.y;
            acc[j].z += kf[j] * vv.z;
            acc[j].w += kf[j] * vv.w;
        }
    }

    float* ob = g_kvp + ((size_t)bh * 32 + ch) * 4096;
#pragma unroll
    for (int j = 0; j < 16; j++)
        *(float4*)(ob + (dg * 16 + j) * 64 + mg * 4) = acc[j];
}

// ksum partials: grid (64, 4), block 256
__global__ __launch_bounds__(256) void ksum_part()
{
    const int bh = blockIdx.x;
    const int grp = blockIdx.y;
    const int b = bh >> 3, h = bh & 7;
    const int tid = threadIdx.x;
    const int d = tid & 63, sg = tid >> 6;

    float s = 0.f;
    const float* kp = g_k + ((size_t)b * S_) * 512 + h * 64 + d;
#pragma unroll 4
    for (int s0 = grp * 1024 + sg; s0 < (grp + 1) * 1024; s0 += 4)
        s += kp[(size_t)s0 * 512];

    __shared__ float red[256];
    red[tid] = s;
    __syncthreads();
    if (sg == 0)
        g_ksp[(bh * 4 + grp) * 64 + d] = red[d] + red[64 + d] + red[128 + d] + red[192 + d];
}

// reduce chunks; writes g_kv TRANSPOSED [bh][m][d]; finishes ksum. grid 64, block 256.
__global__ __launch_bounds__(256) void kv_reduce()
{
    const int bh = blockIdx.x;
    const int tid = threadIdx.x;
    for (int idx = tid; idx < 4096; idx += 256) {
        float s = 0.f;
#pragma unroll
        for (int c = 0; c < 32; c++)
            s += g_kvp[((size_t)bh * 32 + c) * 4096 + idx];
        // idx = d*64 + m  ->  store at m*64 + d
        g_kv[(size_t)bh * 4096 + (idx & 63) * 64 + (idx >> 6)] = s;
    }
    if (tid < 64) {
        float s = g_ksp[(bh * 4 + 0) * 64 + tid] + g_ksp[(bh * 4 + 1) * 64 + tid]
                + g_ksp[(bh * 4 + 2) * 64 + tid] + g_ksp[(bh * 4 + 3) * 64 + tid];
        g_ksum[bh * 64 + tid] = s;
    }
}

// ============================================================
// Attention readout (vectorized; kv is [m][d]) -> bf16 hi/lo for out GEMM
__global__ __launch_bounds__(512) void attn_kernel()
{
    const int b = blockIdx.y;
    const int l0 = blockIdx.x * 8;
    const int tid = threadIdx.x;
    const int h = tid >> 6, m = tid & 63;

    __shared__ __align__(16) float qs[8][512];
    __shared__ __align__(16) float kss[512];

#pragma unroll
    for (int r = 0; r < 8; r++)
        qs[r][tid] = g_q[((size_t)(b * S_ + l0 + r)) * 512 + tid];
    kss[tid] = g_ksum[b * 512 + tid];
    __syncthreads();

    float acc[8], denom[8];
#pragma unroll
    for (int r = 0; r < 8; r++) { acc[r] = 0.f; denom[r] = 0.f; }

    const float* kvp = g_kv + ((size_t)(b * 8 + h)) * 4096 + m * 64;
#pragma unroll
    for (int d4 = 0; d4 < 16; d4++) {
        float4 kv4 = *(const float4*)(kvp + d4 * 4);
        float4 ks4 = *(const float4*)(&kss[h * 64 + d4 * 4]);
#pragma unroll
        for (int r = 0; r < 8; r++) {
            float4 q4 = *(const float4*)(&qs[r][h * 64 + d4 * 4]);
            acc[r]   += q4.x * kv4.x + q4.y * kv4.y + q4.z * kv4.z + q4.w * kv4.w;
            denom[r] += q4.x * ks4.x + q4.y * ks4.y + q4.z * ks4.z + q4.w * ks4.w;
        }
    }

#pragma unroll
    for (int r = 0; r < 8; r++) {
        float z = 1.0f / (denom[r] + EPS_);
        float v = acc[r] * z;
        size_t idx = ((size_t)(b * S_ + l0 + r)) * 512 + tid;
        __nv_bfloat16 hi = __float2bfloat16(v);
        g_ah[idx] = hi;
        g_al[idx] = __float2bfloat16(v - __bfloat162float(hi));
    }
}

// ============================================================
extern "C" void kernel_launch(void* const* d_in, const int* in_sizes, int n_in,
                              void* d_out, int out_size)
{
    const float* x  = (const float*)d_in[0];
    const float* Wq = (const float*)d_in[1];
    const float* bq = (const float*)d_in[2];
    const float* Wk = (const float*)d_in[3];
    const float* bk = (const float*)d_in[4];
    const float* Wv = (const float*)d_in[5];
    const float* bv = (const float*)d_in[6];
    const float* Wo = (const float*)d_in[7];
    const float* bo = (const float*)d_in[8];
    float* out = (float*)d_out;

    cudaFuncSetAttribute(qkv_mma, cudaFuncAttributeMaxDynamicSharedMemorySize, GEMM_DSMEM);
    cudaFuncSetAttribute(out_mma, cudaFuncAttributeMaxDynamicSharedMemorySize, GEMM_DSMEM);

    split_x<<<(M_ * E_) / (256 * 4), 256>>>(x);
    tsplit_w<<<dim3(16, 16, 4), dim3(32, 8)>>>(Wq, Wk, Wv, Wo);
    qkv_mma<<<dim3(M_ / 128, 8, 3), 256, GEMM_DSMEM>>>(bq, bk, bv);
    kv_partial<<<dim3(8, 64), 256>>>();
    ksum_part<<<dim3(64, 4), 256>>>();
    kv_reduce<<<64, 256>>>();
    attn_kernel<<<dim3(S_ / 8, B_), 512>>>();
    out_mma<<<dim3(M_ / 128, 8), 256, GEMM_DSMEM>>>(out, bo);
}

// round 7
// speedup vs baseline: 1.3136x; 1.3136x over previous
#include <cuda_runtime.h>
#include <cuda_bf16.h>
#include <math.h>
#include <stdint.h>

#define B_   8
#define S_   4096
#define E_   512
#define H_   8
#define D_   64
#define M_   (B_ * S_)      // 32768 rows
#define EPS_ 1e-6f

// -------- scratch (device globals; no allocations allowed) --------
__device__ __align__(16) float g_q[(size_t)M_ * E_];
__device__ __align__(16) float g_k[(size_t)M_ * E_];
__device__ __align__(16) float g_v[(size_t)M_ * E_];
__device__ __align__(16) float g_kv[B_ * H_ * D_ * D_];           // [bh][m][d] (transposed)
__device__ __align__(16) float g_ksum[B_ * H_ * D_];
__device__ __align__(16) float g_kvp[(size_t)B_ * H_ * 32 * D_ * D_];  // [bh][ch][d][m]
__device__ __align__(16) float g_ksp[B_ * H_ * 32 * D_];               // [bh][ch][d]
// bf16 split operands
__device__ __align__(16) __nv_bfloat16 g_xh[(size_t)M_ * E_];
__device__ __align__(16) __nv_bfloat16 g_xl[(size_t)M_ * E_];
__device__ __align__(16) __nv_bfloat16 g_ah[(size_t)M_ * E_];
__device__ __align__(16) __nv_bfloat16 g_al[(size_t)M_ * E_];
__device__ __align__(16) __nv_bfloat16 g_wh[4 * 512 * 512];  // transposed [n][k]
__device__ __align__(16) __nv_bfloat16 g_wl[4 * 512 * 512];

// ================= portable PTX helpers =================
static __device__ __forceinline__ uint32_t smem_u32(const void* p) {
    uint32_t a;
    asm("{ .reg .u64 t; cvta.to.shared.u64 t, %1; cvt.u32.u64 %0, t; }" : "=r"(a) : "l"(p));
    return a;
}
static __device__ __forceinline__ void ldsm4(uint32_t* r, uint32_t addr) {
    asm volatile("ldmatrix.sync.aligned.m8n8.x4.shared.b16 {%0,%1,%2,%3}, [%4];"
                 : "=r"(r[0]), "=r"(r[1]), "=r"(r[2]), "=r"(r[3]) : "r"(addr));
}
static __device__ __forceinline__ void mma16816(float* c, const uint32_t* a, const uint32_t* b) {
    asm volatile("mma.sync.aligned.m16n8k16.row.col.f32.bf16.bf16.f32 "
                 "{%0,%1,%2,%3}, {%4,%5,%6,%7}, {%8,%9}, {%0,%1,%2,%3};"
                 : "+f"(c[0]), "+f"(c[1]), "+f"(c[2]), "+f"(c[3])
                 : "r"(a[0]), "r"(a[1]), "r"(a[2]), "r"(a[3]), "r"(b[0]), "r"(b[1]));
}

// ============================================================
// HMMA bf16 3-split GEMM (R5 proven): C[m0:+128, n0:+64] = act(A @ B^T + bias)
// A (hi/lo) [M,512] row-major bf16; B (hi/lo) [N=512,512] K-major bf16 ([n][k]).
// 256 threads = 8 warps (4m x 2n), warp tile 32x32, BK=64.
// SMEM 48KB: Ah(16K) | Al(16K) | Bh(8K) | Bl(8K), XOR-swizzled 16B chunks.
// ============================================================
static __device__ __forceinline__ void gemm_mma_body(
    const __nv_bfloat16* __restrict__ Ah, const __nv_bfloat16* __restrict__ Al,
    const __nv_bfloat16* __restrict__ Bh, const __nv_bfloat16* __restrict__ Bl,
    const float* __restrict__ bias, float* __restrict__ C,
    bool act, int m0, int n0)
{
    __shared__ __align__(1024) uint8_t sm[49152];
    const int tid = threadIdx.x;
    const int wid = tid >> 5, lane = tid & 31;
    const int wm = wid & 3;
    const int wn = wid >> 2;
    const uint32_t sbase = smem_u32(sm);
    const uint32_t sAh = sbase, sAl = sbase + 16384;
    const uint32_t sBh = sbase + 32768, sBl = sbase + 40960;

    float acc[2][4][4];
#pragma unroll
    for (int i = 0; i < 2; i++)
#pragma unroll
        for (int j = 0; j < 4; j++)
#pragma unroll
            for (int t = 0; t < 4; t++) acc[i][j][t] = 0.f;

    const int rA  = wm * 32 + (lane & 15);
    const int khA = (lane >> 4) & 1;
    const int rB  = wn * 32 + (lane & 7) + ((lane >> 1) & 8);
    const int khB = (lane >> 3) & 1;
    const int swA = rA & 7;
    const int swB = rB & 7;

    const char* Ahb = (const char*)Ah;
    const char* Alb = (const char*)Al;
    const char* Bhb = (const char*)Bh;
    const char* Blb = (const char*)Bl;

    for (int kb = 0; kb < 8; kb++) {
        const int k0 = kb * 64;
#pragma unroll
        for (int i = 0; i < 4; i++) {
            int idx = i * 256 + tid;
            int r = idx >> 3, c = idx & 7;
            uint32_t so = (uint32_t)(r * 128 + ((c ^ (r & 7)) << 4));
            size_t go = ((size_t)(m0 + r) * 512 + k0) * 2 + c * 16;
            *(uint4*)(sm + so)         = *(const uint4*)(Ahb + go);
            *(uint4*)(sm + 16384 + so) = *(const uint4*)(Alb + go);
        }
#pragma unroll
        for (int i = 0; i < 2; i++) {
            int idx = i * 256 + tid;
            int r = idx >> 3, c = idx & 7;
            uint32_t so = (uint32_t)(r * 128 + ((c ^ (r & 7)) << 4));
            size_t go = ((size_t)(n0 + r) * 512 + k0) * 2 + c * 16;
            *(uint4*)(sm + 32768 + so) = *(const uint4*)(Bhb + go);
            *(uint4*)(sm + 40960 + so) = *(const uint4*)(Blb + go);
        }
        __syncthreads();

#pragma unroll
        for (int ks = 0; ks < 4; ks++) {
            uint32_t aH[8], aL[8], bH[8], bL[8];
            int cA = ks * 2 + khA;
            uint32_t aoff = (uint32_t)(rA * 128 + ((cA ^ swA) << 4));
            int cB = ks * 2 + khB;
            uint32_t boff = (uint32_t)(rB * 128 + ((cB ^ swB) << 4));

            ldsm4(aH + 0, sAh + aoff);
            ldsm4(aH + 4, sAh + aoff + 2048);
            ldsm4(bH + 0, sBh + boff);
            ldsm4(bH + 4, sBh + boff + 2048);
#pragma unroll
            for (int mt = 0; mt < 2; mt++)
#pragma unroll
                for (int nt = 0; nt < 4; nt++)
                    mma16816(acc[mt][nt], aH + 4 * mt, bH + nt * 2);

            ldsm4(aL + 0, sAl + aoff);
            ldsm4(aL + 4, sAl + aoff + 2048);
#pragma unroll
            for (int mt = 0; mt < 2; mt++)
#pragma unroll
                for (int nt = 0; nt < 4; nt++)
                    mma16816(acc[mt][nt], aL + 4 * mt, bH + nt * 2);

            ldsm4(bL + 0, sBl + boff);
            ldsm4(bL + 4, sBl + boff + 2048);
#pragma unroll
            for (int mt = 0; mt < 2; mt++)
#pragma unroll
                for (int nt = 0; nt < 4; nt++)
                    mma16816(acc[mt][nt], aH + 4 * mt, bL + nt * 2);
        }
        __syncthreads();
    }

    const int g = lane >> 2, t4 = lane & 3;
#pragma unroll
    for (int mt = 0; mt < 2; mt++) {
#pragma unroll
        for (int nt = 0; nt < 4; nt++) {
            int row = m0 + wm * 32 + mt * 16 + g;
            int col = n0 + wn * 32 + nt * 8 + t4 * 2;
            float b0 = bias[col], b1 = bias[col + 1];
            float f0 = acc[mt][nt][0] + b0;
            float f1 = acc[mt][nt][1] + b1;
            float f2 = acc[mt][nt][2] + b0;
            float f3 = acc[mt][nt][3] + b1;
            if (act) {
                f0 = (f0 > 0.f) ? (f0 + 1.f) : __expf(f0);
                f1 = (f1 > 0.f) ? (f1 + 1.f) : __expf(f1);
                f2 = (f2 > 0.f) ? (f2 + 1.f) : __expf(f2);
                f3 = (f3 > 0.f) ? (f3 + 1.f) : __expf(f3);
            }
            *(float2*)(C + (size_t)row * 512 + col)       = make_float2(f0, f1);
            *(float2*)(C + (size_t)(row + 8) * 512 + col) = make_float2(f2, f3);
        }
    }
}

// grid (256, 8, 3): z = matrix (0=Q,1=K,2=V), y = n-tile of 64
__global__ __launch_bounds__(256, 2) void qkv_mma(const float* __restrict__ bq,
                                                  const float* __restrict__ bk,
                                                  const float* __restrict__ bv)
{
    int mat = blockIdx.z;
    const __nv_bfloat16* Bh = g_wh + (size_t)mat * 262144;
    const __nv_bfloat16* Bl = g_wl + (size_t)mat * 262144;
    const float* bias = (mat == 0) ? bq : (mat == 1) ? bk : bv;
    float* C = (mat == 0) ? g_q : (mat == 1) ? g_k : g_v;
    gemm_mma_body(g_xh, g_xl, Bh, Bl, bias, C, mat < 2,
                  blockIdx.x * 128, blockIdx.y * 64);
}

// grid (256, 8)
__global__ __launch_bounds__(256, 2) void out_mma(float* __restrict__ out,
                                                  const float* __restrict__ bo)
{
    gemm_mma_body(g_ah, g_al, g_wh + (size_t)3 * 262144, g_wl + (size_t)3 * 262144,
                  bo, out, false, blockIdx.x * 128, blockIdx.y * 64);
}

// ============================================================
// split x -> bf16 hi/lo
__global__ __launch_bounds__(256) void split_x(const float* __restrict__ x)
{
    size_t i4 = ((size_t)blockIdx.x * 256 + threadIdx.x) * 4;
    float4 v = *(const float4*)(x + i4);
    float vv[4] = {v.x, v.y, v.z, v.w};
    __nv_bfloat16 h[4], l[4];
#pragma unroll
    for (int j = 0; j < 4; j++) {
        h[j] = __float2bfloat16(vv[j]);
        l[j] = __float2bfloat16(vv[j] - __bfloat162float(h[j]));
    }
    *(__nv_bfloat162*)(g_xh + i4)     = __nv_bfloat162(h[0], h[1]);
    *(__nv_bfloat162*)(g_xh + i4 + 2) = __nv_bfloat162(h[2], h[3]);
    *(__nv_bfloat162*)(g_xl + i4)     = __nv_bfloat162(l[0], l[1]);
    *(__nv_bfloat162*)(g_xl + i4 + 2) = __nv_bfloat162(l[2], l[3]);
}

// transpose + split weights
__global__ __launch_bounds__(256) void tsplit_w(const float* __restrict__ Wq,
                                                const float* __restrict__ Wk,
                                                const float* __restrict__ Wv,
                                                const float* __restrict__ Wo)
{
    const float* W = (blockIdx.z == 0) ? Wq : (blockIdx.z == 1) ? Wk
                   : (blockIdx.z == 2) ? Wv : Wo;
    __nv_bfloat16* oh = g_wh + (size_t)blockIdx.z * 262144;
    __nv_bfloat16* ol = g_wl + (size_t)blockIdx.z * 262144;
    __shared__ float t[32][33];
    int nx = blockIdx.x * 32 + threadIdx.x;
    int k0 = blockIdx.y * 32;
#pragma unroll
    for (int j = 0; j < 4; j++)
        t[threadIdx.y + j * 8][threadIdx.x] = W[(size_t)(k0 + threadIdx.y + j * 8) * 512 + nx];
    __syncthreads();
#pragma unroll
    for (int j = 0; j < 4; j++) {
        int nr = blockIdx.x * 32 + threadIdx.y + j * 8;
        int kc = k0 + threadIdx.x;
        float v = t[threadIdx.x][threadIdx.y + j * 8];
        __nv_bfloat16 h = __float2bfloat16(v);
        oh[(size_t)nr * 512 + kc] = h;
        ol[(size_t)nr * 512 + kc] = __float2bfloat16(v - __bfloat162float(h));
    }
}

// ============================================================
// KV partials + fused ksum: register outer-product, no barriers.
// grid (16, 64) block 256. Two 128-row chunks per CTA (tid>>7).
// Thread: 8 d x 4 m tile. 128 threads cover 64x64 per chunk.
__global__ __launch_bounds__(256) void kv_partial()
{
    const int bh = blockIdx.y;
    const int b = bh >> 3, h = bh & 7;
    const int tid = threadIdx.x;
    const int ch = blockIdx.x * 2 + (tid >> 7);
    const int t128 = tid & 127;
    const int dg = t128 >> 4;    // 0..7 -> d base = dg*8
    const int mg = t128 & 15;    // m base = mg*4

    const size_t base = ((size_t)(b * S_ + ch * 128)) * 512 + h * 64;
    const float* kbase = g_k + base + dg * 8;
    const float* vbase = g_v + base + mg * 4;

    float4 acc[8];
#pragma unroll
    for (int j = 0; j < 8; j++) acc[j] = make_float4(0.f, 0.f, 0.f, 0.f);
    float ks[8];
#pragma unroll
    for (int j = 0; j < 8; j++) ks[j] = 0.f;

#pragma unroll 4
    for (int s = 0; s < 128; s++) {
        const float4* kp = (const float4*)(kbase + (size_t)s * 512);
        float4 k0 = kp[0], k1 = kp[1];
        float4 vv = *(const float4*)(vbase + (size_t)s * 512);
        float kf[8] = {k0.x, k0.y, k0.z, k0.w, k1.x, k1.y, k1.z, k1.w};
#pragma unroll
        for (int j = 0; j < 8; j++) {
            acc[j].x += kf[j] * vv.x;
            acc[j].y += kf[j] * vv.y;
            acc[j].z += kf[j] * vv.z;
            acc[j].w += kf[j] * vv.w;
        }
        if (mg == 0) {
#pragma unroll
            for (int j = 0; j < 8; j++) ks[j] += kf[j];
        }
    }

    float* ob = g_kvp + ((size_t)bh * 32 + ch) * 4096;
#pragma unroll
    for (int j = 0; j < 8; j++)
        *(float4*)(ob + (dg * 8 + j) * 64 + mg * 4) = acc[j];
    if (mg == 0) {
        float* kb = g_ksp + ((size_t)bh * 32 + ch) * 64 + dg * 8;
#pragma unroll
        for (int j = 0; j < 8; j++) kb[j] = ks[j];
    }
}

// reduce chunks; writes g_kv TRANSPOSED [bh][m][d]; finishes ksum. grid 64, block 256.
__global__ __launch_bounds__(256) void kv_reduce()
{
    const int bh = blockIdx.x;
    const int tid = threadIdx.x;
    for (int idx = tid; idx < 4096; idx += 256) {
        float s = 0.f;
#pragma unroll
        for (int c = 0; c < 32; c++)
            s += g_kvp[((size_t)bh * 32 + c) * 4096 + idx];
        // idx = d*64 + m  ->  store at m*64 + d
        g_kv[(size_t)bh * 4096 + (idx & 63) * 64 + (idx >> 6)] = s;
    }
    if (tid < 64) {
        float s = 0.f;
#pragma unroll
        for (int c = 0; c < 32; c++)
            s += g_ksp[((size_t)bh * 32 + c) * 64 + tid];
        g_ksum[bh * 64 + tid] = s;
    }
}

// ============================================================
// Attention readout (vectorized; kv is [m][d]) -> bf16 hi/lo for out GEMM
__global__ __launch_bounds__(512) void attn_kernel()
{
    const int b = blockIdx.y;
    const int l0 = blockIdx.x * 8;
    const int tid = threadIdx.x;
    const int h = tid >> 6, m = tid & 63;

    __shared__ __align__(16) float qs[8][512];
    __shared__ __align__(16) float kss[512];

#pragma unroll
    for (int r = 0; r < 8; r++)
        qs[r][tid] = g_q[((size_t)(b * S_ + l0 + r)) * 512 + tid];
    kss[tid] = g_ksum[b * 512 + tid];
    __syncthreads();

    float acc[8], denom[8];
#pragma unroll
    for (int r = 0; r < 8; r++) { acc[r] = 0.f; denom[r] = 0.f; }

    const float* kvp = g_kv + ((size_t)(b * 8 + h)) * 4096 + m * 64;
#pragma unroll
    for (int d4 = 0; d4 < 16; d4++) {
        float4 kv4 = *(const float4*)(kvp + d4 * 4);
        float4 ks4 = *(const float4*)(&kss[h * 64 + d4 * 4]);
#pragma unroll
        for (int r = 0; r < 8; r++) {
            float4 q4 = *(const float4*)(&qs[r][h * 64 + d4 * 4]);
            acc[r]   += q4.x * kv4.x + q4.y * kv4.y + q4.z * kv4.z + q4.w * kv4.w;
            denom[r] += q4.x * ks4.x + q4.y * ks4.y + q4.z * ks4.z + q4.w * ks4.w;
        }
    }

#pragma unroll
    for (int r = 0; r < 8; r++) {
        float z = 1.0f / (denom[r] + EPS_);
        float v = acc[r] * z;
        size_t idx = ((size_t)(b * S_ + l0 + r)) * 512 + tid;
        __nv_bfloat16 hi = __float2bfloat16(v);
        g_ah[idx] = hi;
        g_al[idx] = __float2bfloat16(v - __bfloat162float(hi));
    }
}

// ============================================================
extern "C" void kernel_launch(void* const* d_in, const int* in_sizes, int n_in,
                              void* d_out, int out_size)
{
    const float* x  = (const float*)d_in[0];
    const float* Wq = (const float*)d_in[1];
    const float* bq = (const float*)d_in[2];
    const float* Wk = (const float*)d_in[3];
    const float* bk = (const float*)d_in[4];
    const float* Wv = (const float*)d_in[5];
    const float* bv = (const float*)d_in[6];
    const float* Wo = (const float*)d_in[7];
    const float* bo = (const float*)d_in[8];
    float* out = (float*)d_out;

    split_x<<<(M_ * E_) / (256 * 4), 256>>>(x);
    tsplit_w<<<dim3(16, 16, 4), dim3(32, 8)>>>(Wq, Wk, Wv, Wo);
    qkv_mma<<<dim3(M_ / 128, 8, 3), 256>>>(bq, bk, bv);
    kv_partial<<<dim3(16, 64), 256>>>();
    kv_reduce<<<64, 256>>>();
    attn_kernel<<<dim3(S_ / 8, B_), 512>>>();
    out_mma<<<dim3(M_ / 128, 8), 256>>>(out, bo);
}

// round 8
// speedup vs baseline: 2.1950x; 1.6710x over previous
#include <cuda_runtime.h>
#include <cuda_fp16.h>
#include <math.h>
#include <stdint.h>

#define B_   8
#define S_   4096
#define E_   512
#define H_   8
#define D_   64
#define M_   (B_ * S_)      // 32768 rows
#define EPS_ 1e-6f

// -------- scratch (device globals; no allocations allowed) --------
__device__ __align__(16) float g_q[(size_t)M_ * E_];
__device__ __align__(16) float g_k[(size_t)M_ * E_];
__device__ __align__(16) float g_v[(size_t)M_ * E_];
__device__ __align__(16) float g_kv[B_ * H_ * D_ * D_];           // [bh][d][m]
__device__ __align__(16) float g_ksum[B_ * H_ * D_];
__device__ __align__(16) float g_kvp[(size_t)B_ * H_ * 32 * D_ * D_];  // [bh][ch][d][m]
__device__ __align__(16) float g_ksp[B_ * H_ * 32 * D_];               // [bh][ch][d]
// fp16 operands
__device__ __align__(16) __half g_x16[(size_t)M_ * E_];
__device__ __align__(16) __half g_a16[(size_t)M_ * E_];
__device__ __align__(16) __half g_w16[4 * 512 * 512];   // transposed [n][k]

// ================= portable PTX helpers =================
static __device__ __forceinline__ uint32_t smem_u32(const void* p) {
    uint32_t a;
    asm("{ .reg .u64 t; cvta.to.shared.u64 t, %1; cvt.u32.u64 %0, t; }" : "=r"(a) : "l"(p));
    return a;
}
static __device__ __forceinline__ void ldsm4(uint32_t* r, uint32_t addr) {
    asm volatile("ldmatrix.sync.aligned.m8n8.x4.shared.b16 {%0,%1,%2,%3}, [%4];"
                 : "=r"(r[0]), "=r"(r[1]), "=r"(r[2]), "=r"(r[3]) : "r"(addr));
}
static __device__ __forceinline__ void mma16816(float* c, const uint32_t* a, const uint32_t* b) {
    asm volatile("mma.sync.aligned.m16n8k16.row.col.f32.f16.f16.f32 "
                 "{%0,%1,%2,%3}, {%4,%5,%6,%7}, {%8,%9}, {%0,%1,%2,%3};"
                 : "+f"(c[0]), "+f"(c[1]), "+f"(c[2]), "+f"(c[3])
                 : "r"(a[0]), "r"(a[1]), "r"(a[2]), "r"(a[3]), "r"(b[0]), "r"(b[1]));
}

// ============================================================
// HMMA fp16 single-pass GEMM: C[m0:+128, n0:+64] = act(A @ B^T + bias)
// A [M,512] row-major fp16; B [N=512,512] K-major fp16 ([n][k]).
// 256 threads = 8 warps (4m x 2n), warp tile 32x32. Outer BK=128 (2 x 64-k
// subtiles resident). SMEM 48KB: A0(16K) A1(16K) B0(8K) B1(8K), XOR swizzle.
// ============================================================
static __device__ __forceinline__ void gemm_mma_body(
    const __half* __restrict__ A, const __half* __restrict__ Bm,
    const float* __restrict__ bias, float* __restrict__ C,
    bool act, int m0, int n0)
{
    __shared__ __align__(1024) uint8_t sm[49152];
    const int tid = threadIdx.x;
    const int wid = tid >> 5, lane = tid & 31;
    const int wm = wid & 3;
    const int wn = wid >> 2;
    const uint32_t sbase = smem_u32(sm);

    float acc[2][4][4];
#pragma unroll
    for (int i = 0; i < 2; i++)
#pragma unroll
        for (int j = 0; j < 4; j++)
#pragma unroll
            for (int t = 0; t < 4; t++) acc[i][j][t] = 0.f;

    const int rA  = wm * 32 + (lane & 15);
    const int khA = (lane >> 4) & 1;
    const int rB  = wn * 32 + (lane & 7) + ((lane >> 1) & 8);
    const int khB = (lane >> 3) & 1;
    const int swA = rA & 7;
    const int swB = rB & 7;

    const char* Ab = (const char*)A;
    const char* Bb = (const char*)Bm;

    for (int kb = 0; kb < 4; kb++) {
        const int k0 = kb * 128;
        // A: two 64-k subtiles, 128 rows x 128B each -> 2048 16B-chunks
#pragma unroll
        for (int i = 0; i < 8; i++) {
            int idx = i * 256 + tid;
            int s = idx >> 10, rem = idx & 1023;
            int r = rem >> 3, c = rem & 7;
            uint32_t so = (uint32_t)(s * 16384 + r * 128 + ((c ^ (r & 7)) << 4));
            size_t go = ((size_t)(m0 + r) * 512 + k0 + s * 64) * 2 + c * 16;
            *(uint4*)(sm + so) = *(const uint4*)(Ab + go);
        }
        // B: two 64-k subtiles, 64 rows x 128B each -> 1024 chunks
#pragma unroll
        for (int i = 0; i < 4; i++) {
            int idx = i * 256 + tid;
            int s = idx >> 9, rem = idx & 511;
            int r = rem >> 3, c = rem & 7;
            uint32_t so = (uint32_t)(32768 + s * 8192 + r * 128 + ((c ^ (r & 7)) << 4));
            size_t go = ((size_t)(n0 + r) * 512 + k0 + s * 64) * 2 + c * 16;
            *(uint4*)(sm + so) = *(const uint4*)(Bb + go);
        }
        __syncthreads();

#pragma unroll
        for (int sub = 0; sub < 2; sub++) {
            const uint32_t sA = sbase + sub * 16384;
            const uint32_t sB = sbase + 32768 + sub * 8192;
#pragma unroll
            for (int ks = 0; ks < 4; ks++) {
                uint32_t a[8], b[8];
                int cA = ks * 2 + khA;
                uint32_t aoff = (uint32_t)(rA * 128 + ((cA ^ swA) << 4));
                int cB = ks * 2 + khB;
                uint32_t boff = (uint32_t)(rB * 128 + ((cB ^ swB) << 4));

                ldsm4(a + 0, sA + aoff);
                ldsm4(a + 4, sA + aoff + 2048);
                ldsm4(b + 0, sB + boff);
                ldsm4(b + 4, sB + boff + 2048);
#pragma unroll
                for (int mt = 0; mt < 2; mt++)
#pragma unroll
                    for (int nt = 0; nt < 4; nt++)
                        mma16816(acc[mt][nt], a + 4 * mt, b + nt * 2);
            }
        }
        __syncthreads();
    }

    const int g = lane >> 2, t4 = lane & 3;
#pragma unroll
    for (int mt = 0; mt < 2; mt++) {
#pragma unroll
        for (int nt = 0; nt < 4; nt++) {
            int row = m0 + wm * 32 + mt * 16 + g;
            int col = n0 + wn * 32 + nt * 8 + t4 * 2;
            float b0 = bias[col], b1 = bias[col + 1];
            float f0 = acc[mt][nt][0] + b0;
            float f1 = acc[mt][nt][1] + b1;
            float f2 = acc[mt][nt][2] + b0;
            float f3 = acc[mt][nt][3] + b1;
            if (act) {
                f0 = (f0 > 0.f) ? (f0 + 1.f) : __expf(f0);
                f1 = (f1 > 0.f) ? (f1 + 1.f) : __expf(f1);
                f2 = (f2 > 0.f) ? (f2 + 1.f) : __expf(f2);
                f3 = (f3 > 0.f) ? (f3 + 1.f) : __expf(f3);
            }
            *(float2*)(C + (size_t)row * 512 + col)       = make_float2(f0, f1);
            *(float2*)(C + (size_t)(row + 8) * 512 + col) = make_float2(f2, f3);
        }
    }
}

// grid (256, 8, 3): z = matrix (0=Q,1=K,2=V), y = n-tile of 64
__global__ __launch_bounds__(256, 2) void qkv_mma(const float* __restrict__ bq,
                                                  const float* __restrict__ bk,
                                                  const float* __restrict__ bv)
{
    int mat = blockIdx.z;
    const __half* Bm = g_w16 + (size_t)mat * 262144;
    const float* bias = (mat == 0) ? bq : (mat == 1) ? bk : bv;
    float* C = (mat == 0) ? g_q : (mat == 1) ? g_k : g_v;
    gemm_mma_body(g_x16, Bm, bias, C, mat < 2, blockIdx.x * 128, blockIdx.y * 64);
}

// grid (256, 8)
__global__ __launch_bounds__(256, 2) void out_mma(float* __restrict__ out,
                                                  const float* __restrict__ bo)
{
    gemm_mma_body(g_a16, g_w16 + (size_t)3 * 262144, bo, out, false,
                  blockIdx.x * 128, blockIdx.y * 64);
}

// ============================================================
// x -> fp16
__global__ __launch_bounds__(256) void split_x(const float* __restrict__ x)
{
    size_t i4 = ((size_t)blockIdx.x * 256 + threadIdx.x) * 4;
    float4 v = *(const float4*)(x + i4);
    __half2 h0 = __floats2half2_rn(v.x, v.y);
    __half2 h1 = __floats2half2_rn(v.z, v.w);
    *(__half2*)(g_x16 + i4)     = h0;
    *(__half2*)(g_x16 + i4 + 2) = h1;
}

// transpose weights: W [k][n] fp32 -> Wt [n][k] fp16. grid(16,16,4) block(32,8)
__global__ __launch_bounds__(256) void tsplit_w(const float* __restrict__ Wq,
                                                const float* __restrict__ Wk,
                                                const float* __restrict__ Wv,
                                                const float* __restrict__ Wo)
{
    const float* W = (blockIdx.z == 0) ? Wq : (blockIdx.z == 1) ? Wk
                   : (blockIdx.z == 2) ? Wv : Wo;
    __half* oh = g_w16 + (size_t)blockIdx.z * 262144;
    __shared__ float t[32][33];
    int nx = blockIdx.x * 32 + threadIdx.x;
    int k0 = blockIdx.y * 32;
#pragma unroll
    for (int j = 0; j < 4; j++)
        t[threadIdx.y + j * 8][threadIdx.x] = W[(size_t)(k0 + threadIdx.y + j * 8) * 512 + nx];
    __syncthreads();
#pragma unroll
    for (int j = 0; j < 4; j++) {
        int nr = blockIdx.x * 32 + threadIdx.y + j * 8;
        int kc = k0 + threadIdx.x;
        oh[(size_t)nr * 512 + kc] = __float2half(t[threadIdx.x][threadIdx.y + j * 8]);
    }
}

// ============================================================
// KV partials + fused ksum (R7 proven): grid (16, 64) block 256.
__global__ __launch_bounds__(256) void kv_partial()
{
    const int bh = blockIdx.y;
    const int b = bh >> 3, h = bh & 7;
    const int tid = threadIdx.x;
    const int ch = blockIdx.x * 2 + (tid >> 7);
    const int t128 = tid & 127;
    const int dg = t128 >> 4;    // d base = dg*8
    const int mg = t128 & 15;    // m base = mg*4

    const size_t base = ((size_t)(b * S_ + ch * 128)) * 512 + h * 64;
    const float* kbase = g_k + base + dg * 8;
    const float* vbase = g_v + base + mg * 4;

    float4 acc[8];
#pragma unroll
    for (int j = 0; j < 8; j++) acc[j] = make_float4(0.f, 0.f, 0.f, 0.f);
    float ks[8];
#pragma unroll
    for (int j = 0; j < 8; j++) ks[j] = 0.f;

#pragma unroll 4
    for (int s = 0; s < 128; s++) {
        const float4* kp = (const float4*)(kbase + (size_t)s * 512);
        float4 k0 = kp[0], k1 = kp[1];
        float4 vv = *(const float4*)(vbase + (size_t)s * 512);
        float kf[8] = {k0.x, k0.y, k0.z, k0.w, k1.x, k1.y, k1.z, k1.w};
#pragma unroll
        for (int j = 0; j < 8; j++) {
            acc[j].x += kf[j] * vv.x;
            acc[j].y += kf[j] * vv.y;
            acc[j].z += kf[j] * vv.z;
            acc[j].w += kf[j] * vv.w;
        }
        if (mg == 0) {
#pragma unroll
            for (int j = 0; j < 8; j++) ks[j] += kf[j];
        }
    }

    float* ob = g_kvp + ((size_t)bh * 32 + ch) * 4096;
#pragma unroll
    for (int j = 0; j < 8; j++)
        *(float4*)(ob + (dg * 8 + j) * 64 + mg * 4) = acc[j];
    if (mg == 0) {
        float* kb = g_ksp + ((size_t)bh * 32 + ch) * 64 + dg * 8;
#pragma unroll
        for (int j = 0; j < 8; j++) kb[j] = ks[j];
    }
}

// reduce chunks (keeps [d][m] layout); finishes ksum. grid 64, block 256.
__global__ __launch_bounds__(256) void kv_reduce()
{
    const int bh = blockIdx.x;
    const int tid = threadIdx.x;
    for (int idx = tid; idx < 4096; idx += 256) {
        float s = 0.f;
#pragma unroll
        for (int c = 0; c < 32; c++)
            s += g_kvp[((size_t)bh * 32 + c) * 4096 + idx];
        g_kv[(size_t)bh * 4096 + idx] = s;
    }
    if (tid < 64) {
        float s = 0.f;
#pragma unroll
        for (int c = 0; c < 32; c++)
            s += g_ksp[((size_t)bh * 32 + c) * 64 + tid];
        g_ksum[bh * 64 + tid] = s;
    }
}

// ============================================================
// Attention readout (R5 coalesced form; kv is [d][m]) -> fp16 for out GEMM
__global__ __launch_bounds__(512) void attn_kernel()
{
    const int b = blockIdx.y;
    const int l0 = blockIdx.x * 8;
    const int tid = threadIdx.x;
    const int h = tid >> 6, m = tid & 63;

    __shared__ __align__(16) float qs[8][512];
    __shared__ __align__(16) float kss[512];

#pragma unroll
    for (int r = 0; r < 8; r++)
        qs[r][tid] = g_q[((size_t)(b * S_ + l0 + r)) * 512 + tid];
    kss[tid] = g_ksum[b * 512 + tid];
    __syncthreads();

    float acc[8], denom[8];
#pragma unroll
    for (int r = 0; r < 8; r++) { acc[r] = 0.f; denom[r] = 0.f; }

    const float* kvp = g_kv + ((size_t)(b * 8 + h)) * 4096 + m;
#pragma unroll 4
    for (int d = 0; d < 64; d++) {
        float kvv = kvp[(size_t)d * 64];
        float ksv = kss[h * 64 + d];
#pragma unroll
        for (int r = 0; r < 8; r++) {
            float qv = qs[r][h * 64 + d];
            acc[r]   += qv * kvv;
            denom[r] += qv * ksv;
        }
    }

#pragma unroll
    for (int r = 0; r < 8; r++) {
        float z = 1.0f / (denom[r] + EPS_);
        float v = acc[r] * z;
        g_a16[((size_t)(b * S_ + l0 + r)) * 512 + tid] = __float2half(v);
    }
}

// ============================================================
extern "C" void kernel_launch(void* const* d_in, const int* in_sizes, int n_in,
                              void* d_out, int out_size)
{
    const float* x  = (const float*)d_in[0];
    const float* Wq = (const float*)d_in[1];
    const float* bq = (const float*)d_in[2];
    const float* Wk = (const float*)d_in[3];
    const float* bk = (const float*)d_in[4];
    const float* Wv = (const float*)d_in[5];
    const float* bv = (const float*)d_in[6];
    const float* Wo = (const float*)d_in[7];
    const float* bo = (const float*)d_in[8];
    float* out = (float*)d_out;

    split_x<<<(M_ * E_) / (256 * 4), 256>>>(x);
    tsplit_w<<<dim3(16, 16, 4), dim3(32, 8)>>>(Wq, Wk, Wv, Wo);
    qkv_mma<<<dim3(M_ / 128, 8, 3), 256>>>(bq, bk, bv);
    kv_partial<<<dim3(16, 64), 256>>>();
    kv_reduce<<<64, 256>>>();
    attn_kernel<<<dim3(S_ / 8, B_), 512>>>();
    out_mma<<<dim3(M_ / 128, 8), 256>>>(out, bo);
}

// round 9
// speedup vs baseline: 2.6776x; 1.2199x over previous
#include <cuda_runtime.h>
#include <cuda_fp16.h>
#include <math.h>
#include <stdint.h>

#define B_   8
#define S_   4096
#define E_   512
#define H_   8
#define D_   64
#define M_   (B_ * S_)      // 32768 rows
#define EPS_ 1e-6f

// -------- scratch (device globals; no allocations allowed) --------
__device__ __align__(16) float g_kv[B_ * H_ * D_ * D_];                // [bh][d][m]
__device__ __align__(16) float g_ksum[B_ * H_ * D_];
__device__ __align__(16) float g_kvp[(size_t)B_ * H_ * 16 * D_ * D_];  // [bh][16][d][m]
__device__ __align__(16) float g_ksp[B_ * H_ * 4 * D_];                // [bh][4][d]
// fp16 operands
__device__ __align__(16) __half g_x16[(size_t)M_ * E_];
__device__ __align__(16) __half g_q16[(size_t)M_ * E_];
__device__ __align__(16) __half g_k16[(size_t)M_ * E_];
__device__ __align__(16) __half g_v16[(size_t)M_ * E_];
__device__ __align__(16) __half g_a16[(size_t)M_ * E_];
__device__ __align__(16) __half g_w16[4 * 512 * 512];   // transposed [n][k]

// ================= portable PTX helpers =================
static __device__ __forceinline__ uint32_t smem_u32(const void* p) {
    uint32_t a;
    asm("{ .reg .u64 t; cvta.to.shared.u64 t, %1; cvt.u32.u64 %0, t; }" : "=r"(a) : "l"(p));
    return a;
}
static __device__ __forceinline__ void ldsm4(uint32_t* r, uint32_t addr) {
    asm volatile("ldmatrix.sync.aligned.m8n8.x4.shared.b16 {%0,%1,%2,%3}, [%4];"
                 : "=r"(r[0]), "=r"(r[1]), "=r"(r[2]), "=r"(r[3]) : "r"(addr));
}
static __device__ __forceinline__ void ldsm4t(uint32_t* r, uint32_t addr) {
    asm volatile("ldmatrix.sync.aligned.m8n8.x4.trans.shared.b16 {%0,%1,%2,%3}, [%4];"
                 : "=r"(r[0]), "=r"(r[1]), "=r"(r[2]), "=r"(r[3]) : "r"(addr));
}
static __device__ __forceinline__ void mma16816(float* c, const uint32_t* a, const uint32_t* b) {
    asm volatile("mma.sync.aligned.m16n8k16.row.col.f32.f16.f16.f32 "
                 "{%0,%1,%2,%3}, {%4,%5,%6,%7}, {%8,%9}, {%0,%1,%2,%3};"
                 : "+f"(c[0]), "+f"(c[1]), "+f"(c[2]), "+f"(c[3])
                 : "r"(a[0]), "r"(a[1]), "r"(a[2]), "r"(a[3]), "r"(b[0]), "r"(b[1]));
}

// ============================================================
// HMMA fp16 GEMM (R8 proven core): C[m0:+128, n0:+64] = act(A @ B^T + bias)
// Output: fp16 (C16) when C16 != nullptr, else fp32 (C32).
// ============================================================
static __device__ __forceinline__ void gemm_mma_body(
    const __half* __restrict__ A, const __half* __restrict__ Bm,
    const float* __restrict__ bias, float* __restrict__ C32,
    __half* __restrict__ C16, bool act, int m0, int n0)
{
    __shared__ __align__(1024) uint8_t sm[49152];
    const int tid = threadIdx.x;
    const int wid = tid >> 5, lane = tid & 31;
    const int wm = wid & 3;
    const int wn = wid >> 2;
    const uint32_t sbase = smem_u32(sm);

    float acc[2][4][4];
#pragma unroll
    for (int i = 0; i < 2; i++)
#pragma unroll
        for (int j = 0; j < 4; j++)
#pragma unroll
            for (int t = 0; t < 4; t++) acc[i][j][t] = 0.f;

    const int rA  = wm * 32 + (lane & 15);
    const int khA = (lane >> 4) & 1;
    const int rB  = wn * 32 + (lane & 7) + ((lane >> 1) & 8);
    const int khB = (lane >> 3) & 1;
    const int swA = rA & 7;
    const int swB = rB & 7;

    const char* Ab = (const char*)A;
    const char* Bb = (const char*)Bm;

    for (int kb = 0; kb < 4; kb++) {
        const int k0 = kb * 128;
#pragma unroll
        for (int i = 0; i < 8; i++) {
            int idx = i * 256 + tid;
            int s = idx >> 10, rem = idx & 1023;
            int r = rem >> 3, c = rem & 7;
            uint32_t so = (uint32_t)(s * 16384 + r * 128 + ((c ^ (r & 7)) << 4));
            size_t go = ((size_t)(m0 + r) * 512 + k0 + s * 64) * 2 + c * 16;
            *(uint4*)(sm + so) = *(const uint4*)(Ab + go);
        }
#pragma unroll
        for (int i = 0; i < 4; i++) {
            int idx = i * 256 + tid;
            int s = idx >> 9, rem = idx & 511;
            int r = rem >> 3, c = rem & 7;
            uint32_t so = (uint32_t)(32768 + s * 8192 + r * 128 + ((c ^ (r & 7)) << 4));
            size_t go = ((size_t)(n0 + r) * 512 + k0 + s * 64) * 2 + c * 16;
            *(uint4*)(sm + so) = *(const uint4*)(Bb + go);
        }
        __syncthreads();

#pragma unroll
        for (int sub = 0; sub < 2; sub++) {
            const uint32_t sA = sbase + sub * 16384;
            const uint32_t sB = sbase + 32768 + sub * 8192;
#pragma unroll
            for (int ks = 0; ks < 4; ks++) {
                uint32_t a[8], b[8];
                int cA = ks * 2 + khA;
                uint32_t aoff = (uint32_t)(rA * 128 + ((cA ^ swA) << 4));
                int cB = ks * 2 + khB;
                uint32_t boff = (uint32_t)(rB * 128 + ((cB ^ swB) << 4));

                ldsm4(a + 0, sA + aoff);
                ldsm4(a + 4, sA + aoff + 2048);
                ldsm4(b + 0, sB + boff);
                ldsm4(b + 4, sB + boff + 2048);
#pragma unroll
                for (int mt = 0; mt < 2; mt++)
#pragma unroll
                    for (int nt = 0; nt < 4; nt++)
                        mma16816(acc[mt][nt], a + 4 * mt, b + nt * 2);
            }
        }
        __syncthreads();
    }

    const int g = lane >> 2, t4 = lane & 3;
#pragma unroll
    for (int mt = 0; mt < 2; mt++) {
#pragma unroll
        for (int nt = 0; nt < 4; nt++) {
            int row = m0 + wm * 32 + mt * 16 + g;
            int col = n0 + wn * 32 + nt * 8 + t4 * 2;
            float b0 = bias[col], b1 = bias[col + 1];
            float f0 = acc[mt][nt][0] + b0;
            float f1 = acc[mt][nt][1] + b1;
            float f2 = acc[mt][nt][2] + b0;
            float f3 = acc[mt][nt][3] + b1;
            if (act) {
                f0 = (f0 > 0.f) ? (f0 + 1.f) : __expf(f0);
                f1 = (f1 > 0.f) ? (f1 + 1.f) : __expf(f1);
                f2 = (f2 > 0.f) ? (f2 + 1.f) : __expf(f2);
                f3 = (f3 > 0.f) ? (f3 + 1.f) : __expf(f3);
            }
            if (C16) {
                *(__half2*)(C16 + (size_t)row * 512 + col)       = __floats2half2_rn(f0, f1);
                *(__half2*)(C16 + (size_t)(row + 8) * 512 + col) = __floats2half2_rn(f2, f3);
            } else {
                *(float2*)(C32 + (size_t)row * 512 + col)       = make_float2(f0, f1);
                *(float2*)(C32 + (size_t)(row + 8) * 512 + col) = make_float2(f2, f3);
            }
        }
    }
}

// grid (256, 8, 3): z = matrix (0=Q,1=K,2=V), y = n-tile of 64. fp16 out.
__global__ __launch_bounds__(256, 2) void qkv_mma(const float* __restrict__ bq,
                                                  const float* __restrict__ bk,
                                                  const float* __restrict__ bv)
{
    int mat = blockIdx.z;
    const __half* Bm = g_w16 + (size_t)mat * 262144;
    const float* bias = (mat == 0) ? bq : (mat == 1) ? bk : bv;
    __half* C = (mat == 0) ? g_q16 : (mat == 1) ? g_k16 : g_v16;
    gemm_mma_body(g_x16, Bm, bias, nullptr, C, mat < 2, blockIdx.x * 128, blockIdx.y * 64);
}

// grid (256, 8). fp32 out.
__global__ __launch_bounds__(256, 2) void out_mma(float* __restrict__ out,
                                                  const float* __restrict__ bo)
{
    gemm_mma_body(g_a16, g_w16 + (size_t)3 * 262144, bo, out, nullptr, false,
                  blockIdx.x * 128, blockIdx.y * 64);
}

// ============================================================
// x -> fp16
__global__ __launch_bounds__(256) void split_x(const float* __restrict__ x)
{
    size_t i4 = ((size_t)blockIdx.x * 256 + threadIdx.x) * 4;
    float4 v = *(const float4*)(x + i4);
    *(__half2*)(g_x16 + i4)     = __floats2half2_rn(v.x, v.y);
    *(__half2*)(g_x16 + i4 + 2) = __floats2half2_rn(v.z, v.w);
}

// transpose weights: W [k][n] fp32 -> Wt [n][k] fp16. grid(16,16,4) block(32,8)
__global__ __launch_bounds__(256) void tsplit_w(const float* __restrict__ Wq,
                                                const float* __restrict__ Wk,
                                                const float* __restrict__ Wv,
                                                const float* __restrict__ Wo)
{
    const float* W = (blockIdx.z == 0) ? Wq : (blockIdx.z == 1) ? Wk
                   : (blockIdx.z == 2) ? Wv : Wo;
    __half* oh = g_w16 + (size_t)blockIdx.z * 262144;
    __shared__ float t[32][33];
    int nx = blockIdx.x * 32 + threadIdx.x;
    int k0 = blockIdx.y * 32;
#pragma unroll
    for (int j = 0; j < 4; j++)
        t[threadIdx.y + j * 8][threadIdx.x] = W[(size_t)(k0 + threadIdx.y + j * 8) * 512 + nx];
    __syncthreads();
#pragma unroll
    for (int j = 0; j < 4; j++) {
        int nr = blockIdx.x * 32 + threadIdx.y + j * 8;
        int kc = k0 + threadIdx.x;
        oh[(size_t)nr * 512 + kc] = __float2half(t[threadIdx.x][threadIdx.y + j * 8]);
    }
}

// ============================================================
// KV state via tensor cores: partial kv[d][m] = sum_s k16[s,d]*v16[s,m].
// grid (4, 64), 256 threads = 8 warps (4 s-subgroups x 2 n-halves).
// CTA covers 1024 s-rows (8 tiles of 128). Warp: rows sub*32..+32 per tile,
// accumulates 64(d) x 32(m) fp32 via mma with ldmatrix.trans fragments.
// Partial index = blockIdx.x*4 + sub  (16 partials per bh).
__global__ __launch_bounds__(256) void kv_mma()
{
    const int bh = blockIdx.y;
    const int b = bh >> 3, h = bh & 7;
    const int tid = threadIdx.x;
    const int wid = tid >> 5, lane = tid & 31;
    const int sub = wid >> 1, nh = wid & 1;

    __shared__ __align__(1024) __half sK[128 * 64];
    __shared__ __align__(1024) __half sV[128 * 64];
    const uint32_t kb = smem_u32(sK), vb = smem_u32(sV);

    float acc[4][4][4];
#pragma unroll
    for (int i = 0; i < 4; i++)
#pragma unroll
        for (int j = 0; j < 4; j++)
#pragma unroll
            for (int t = 0; t < 4; t++) acc[i][j][t] = 0.f;

    const char* gk = (const char*)g_k16 + ((size_t)(b * S_ + blockIdx.x * 1024)) * 1024 + h * 128;
    const char* gv = (const char*)g_v16 + ((size_t)(b * S_ + blockIdx.x * 1024)) * 1024 + h * 128;

    // lane addressing for trans fragments
    const int rAl = ((lane >> 4) & 1) * 8 + (lane & 7);   // A: K^T
    const int cA16 = (lane >> 3) & 1;
    const int rBl = ((lane >> 3) & 1) * 8 + (lane & 7);   // B: V^T
    const int cB16 = (lane >> 4) & 1;

    for (int t = 0; t < 8; t++) {
#pragma unroll
        for (int i = 0; i < 4; i++) {
            int idx = i * 256 + tid;
            int r = idx >> 3, c = idx & 7;
            uint32_t so = (uint32_t)(r * 128 + ((c ^ (r & 7)) << 4));
            size_t go = (size_t)(t * 128 + r) * 1024 + c * 16;
            *(uint4*)((char*)sK + so) = *(const uint4*)(gk + go);
            *(uint4*)((char*)sV + so) = *(const uint4*)(gv + go);
        }
        __syncthreads();

#pragma unroll
        for (int kst = 0; kst < 2; kst++) {
            int s0 = sub * 32 + kst * 16;
            uint32_t a[4][4], bf[2][4];
#pragma unroll
            for (int mt = 0; mt < 4; mt++) {
                int r = s0 + rAl;
                int c = mt * 2 + cA16;
                ldsm4t(a[mt], kb + (uint32_t)(r * 128 + ((c ^ (r & 7)) << 4)));
            }
#pragma unroll
            for (int p = 0; p < 2; p++) {
                int r = s0 + rBl;
                int c = nh * 4 + p * 2 + cB16;
                ldsm4t(bf[p], vb + (uint32_t)(r * 128 + ((c ^ (r & 7)) << 4)));
            }
#pragma unroll
            for (int mt = 0; mt < 4; mt++)
#pragma unroll
                for (int nt = 0; nt < 4; nt++)
                    mma16816(acc[mt][nt], a[mt], &bf[nt >> 1][(nt & 1) * 2]);
        }
        __syncthreads();
    }

    // write 64x32 partial
    float* ob = g_kvp + ((size_t)bh * 16 + blockIdx.x * 4 + sub) * 4096 + nh * 32;
    const int g = lane >> 2, t4 = lane & 3;
#pragma unroll
    for (int mt = 0; mt < 4; mt++) {
#pragma unroll
        for (int nt = 0; nt < 4; nt++) {
            int d = mt * 16 + g, col = nt * 8 + t4 * 2;
            *(float2*)(ob + (size_t)d * 64 + col)       = make_float2(acc[mt][nt][0], acc[mt][nt][1]);
            *(float2*)(ob + (size_t)(d + 8) * 64 + col) = make_float2(acc[mt][nt][2], acc[mt][nt][3]);
        }
    }
}

// ksum partials from fp16 k: grid (64, 4), block 256
__global__ __launch_bounds__(256) void ksum_part()
{
    const int bh = blockIdx.x;
    const int grp = blockIdx.y;
    const int b = bh >> 3, h = bh & 7;
    const int tid = threadIdx.x;
    const int d = tid & 63, sg = tid >> 6;

    float s = 0.f;
    const __half* kp = g_k16 + ((size_t)b * S_) * 512 + h * 64 + d;
#pragma unroll 4
    for (int s0 = grp * 1024 + sg; s0 < (grp + 1) * 1024; s0 += 4)
        s += __half2float(kp[(size_t)s0 * 512]);

    __shared__ float red[256];
    red[tid] = s;
    __syncthreads();
    if (sg == 0)
        g_ksp[(bh * 4 + grp) * 64 + d] = red[d] + red[64 + d] + red[128 + d] + red[192 + d];
}

// reduce 16 kv partials ([d][m] layout) + 4 ksum partials. grid 64, block 256.
__global__ __launch_bounds__(256) void kv_reduce()
{
    const int bh = blockIdx.x;
    const int tid = threadIdx.x;
    for (int idx = tid; idx < 4096; idx += 256) {
        float s = 0.f;
#pragma unroll
        for (int c = 0; c < 16; c++)
            s += g_kvp[((size_t)bh * 16 + c) * 4096 + idx];
        g_kv[(size_t)bh * 4096 + idx] = s;
    }
    if (tid < 64) {
        float s = g_ksp[(bh * 4 + 0) * 64 + tid] + g_ksp[(bh * 4 + 1) * 64 + tid]
                + g_ksp[(bh * 4 + 2) * 64 + tid] + g_ksp[(bh * 4 + 3) * 64 + tid];
        g_ksum[bh * 64 + tid] = s;
    }
}

// ============================================================
// Attention readout (coalesced; kv is [d][m]); q fp16 -> fp32 smem.
__global__ __launch_bounds__(512) void attn_kernel()
{
    const int b = blockIdx.y;
    const int l0 = blockIdx.x * 8;
    const int tid = threadIdx.x;
    const int h = tid >> 6, m = tid & 63;

    __shared__ __align__(16) float qs[8][512];
    __shared__ __align__(16) float kss[512];

#pragma unroll
    for (int it = 0; it < 4; it++) {
        int r = it * 2 + (tid >> 8);
        int i2 = tid & 255;
        __half2 hv = *((const __half2*)(g_q16 + ((size_t)(b * S_ + l0 + r)) * 512) + i2);
        float2 f = __half22float2(hv);
        qs[r][i2 * 2]     = f.x;
        qs[r][i2 * 2 + 1] = f.y;
    }
    kss[tid] = g_ksum[b * 512 + tid];
    __syncthreads();

    float acc[8], denom[8];
#pragma unroll
    for (int r = 0; r < 8; r++) { acc[r] = 0.f; denom[r] = 0.f; }

    const float* kvp = g_kv + ((size_t)(b * 8 + h)) * 4096 + m;
#pragma unroll 4
    for (int d = 0; d < 64; d++) {
        float kvv = kvp[(size_t)d * 64];
        float ksv = kss[h * 64 + d];
#pragma unroll
        for (int r = 0; r < 8; r++) {
            float qv = qs[r][h * 64 + d];
            acc[r]   += qv * kvv;
            denom[r] += qv * ksv;
        }
    }

#pragma unroll
    for (int r = 0; r < 8; r++) {
        float z = 1.0f / (denom[r] + EPS_);
        float v = acc[r] * z;
        g_a16[((size_t)(b * S_ + l0 + r)) * 512 + tid] = __float2half(v);
    }
}

// ============================================================
extern "C" void kernel_launch(void* const* d_in, const int* in_sizes, int n_in,
                              void* d_out, int out_size)
{
    const float* x  = (const float*)d_in[0];
    const float* Wq = (const float*)d_in[1];
    const float* bq = (const float*)d_in[2];
    const float* Wk = (const float*)d_in[3];
    const float* bk = (const float*)d_in[4];
    const float* Wv = (const float*)d_in[5];
    const float* bv = (const float*)d_in[6];
    const float* Wo = (const float*)d_in[7];
    const float* bo = (const float*)d_in[8];
    float* out = (float*)d_out;

    split_x<<<(M_ * E_) / (256 * 4), 256>>>(x);
    tsplit_w<<<dim3(16, 16, 4), dim3(32, 8)>>>(Wq, Wk, Wv, Wo);
    qkv_mma<<<dim3(M_ / 128, 8, 3), 256>>>(bq, bk, bv);
    kv_mma<<<dim3(4, 64), 256>>>();
    ksum_part<<<dim3(64, 4), 256>>>();
    kv_reduce<<<64, 256>>>();
    attn_kernel<<<dim3(S_ / 8, B_), 512>>>();
    out_mma<<<dim3(M_ / 128, 8), 256>>>(out, bo);
}

// round 10
// speedup vs baseline: 3.2555x; 1.2159x over previous
#include <cuda_runtime.h>
#include <cuda_fp16.h>
#include <math.h>
#include <stdint.h>

#define B_   8
#define S_   4096
#define E_   512
#define H_   8
#define D_   64
#define M_   (B_ * S_)      // 32768 rows
#define EPS_ 1e-6f

// -------- scratch (device globals; no allocations allowed) --------
__device__ __align__(16) float g_kvp[(size_t)B_ * H_ * 16 * D_ * D_];  // [bh][16][d][m]
__device__ __align__(16) float g_ksp[B_ * H_ * 4 * D_];                // [bh][4][d]
// KV^T per head, fp16 hi/lo, [bh][80][64]; row 64 = ksum, rows 65-79 zero.
__device__ __align__(16) __half g_kvth[64 * 80 * 64];
__device__ __align__(16) __half g_kvtl[64 * 80 * 64];
// fp16 operands
__device__ __align__(16) __half g_x16[(size_t)M_ * E_];
__device__ __align__(16) __half g_q16[(size_t)M_ * E_];
__device__ __align__(16) __half g_k16[(size_t)M_ * E_];
__device__ __align__(16) __half g_v16[(size_t)M_ * E_];
__device__ __align__(16) __half g_a16[(size_t)M_ * E_];
__device__ __align__(16) __half g_w16[4 * 512 * 512];   // transposed [n][k]

// ================= portable PTX helpers =================
static __device__ __forceinline__ uint32_t smem_u32(const void* p) {
    uint32_t a;
    asm("{ .reg .u64 t; cvta.to.shared.u64 t, %1; cvt.u32.u64 %0, t; }" : "=r"(a) : "l"(p));
    return a;
}
static __device__ __forceinline__ void ldsm4(uint32_t* r, uint32_t addr) {
    asm volatile("ldmatrix.sync.aligned.m8n8.x4.shared.b16 {%0,%1,%2,%3}, [%4];"
                 : "=r"(r[0]), "=r"(r[1]), "=r"(r[2]), "=r"(r[3]) : "r"(addr));
}
static __device__ __forceinline__ void ldsm4t(uint32_t* r, uint32_t addr) {
    asm volatile("ldmatrix.sync.aligned.m8n8.x4.trans.shared.b16 {%0,%1,%2,%3}, [%4];"
                 : "=r"(r[0]), "=r"(r[1]), "=r"(r[2]), "=r"(r[3]) : "r"(addr));
}
static __device__ __forceinline__ void mma16816(float* c, const uint32_t* a, const uint32_t* b) {
    asm volatile("mma.sync.aligned.m16n8k16.row.col.f32.f16.f16.f32 "
                 "{%0,%1,%2,%3}, {%4,%5,%6,%7}, {%8,%9}, {%0,%1,%2,%3};"
                 : "+f"(c[0]), "+f"(c[1]), "+f"(c[2]), "+f"(c[3])
                 : "r"(a[0]), "r"(a[1]), "r"(a[2]), "r"(a[3]), "r"(b[0]), "r"(b[1]));
}

// ============================================================
// HMMA fp16 GEMM (R8 proven core): C[m0:+128, n0:+64] = act(A @ B^T + bias)
// ============================================================
static __device__ __forceinline__ void gemm_mma_body(
    const __half* __restrict__ A, const __half* __restrict__ Bm,
    const float* __restrict__ bias, float* __restrict__ C32,
    __half* __restrict__ C16, bool act, int m0, int n0)
{
    __shared__ __align__(1024) uint8_t sm[49152];
    const int tid = threadIdx.x;
    const int wid = tid >> 5, lane = tid & 31;
    const int wm = wid & 3;
    const int wn = wid >> 2;
    const uint32_t sbase = smem_u32(sm);

    float acc[2][4][4];
#pragma unroll
    for (int i = 0; i < 2; i++)
#pragma unroll
        for (int j = 0; j < 4; j++)
#pragma unroll
            for (int t = 0; t < 4; t++) acc[i][j][t] = 0.f;

    const int rA  = wm * 32 + (lane & 15);
    const int khA = (lane >> 4) & 1;
    const int rB  = wn * 32 + (lane & 7) + ((lane >> 1) & 8);
    const int khB = (lane >> 3) & 1;
    const int swA = rA & 7;
    const int swB = rB & 7;

    const char* Ab = (const char*)A;
    const char* Bb = (const char*)Bm;

    for (int kb = 0; kb < 4; kb++) {
        const int k0 = kb * 128;
#pragma unroll
        for (int i = 0; i < 8; i++) {
            int idx = i * 256 + tid;
            int s = idx >> 10, rem = idx & 1023;
            int r = rem >> 3, c = rem & 7;
            uint32_t so = (uint32_t)(s * 16384 + r * 128 + ((c ^ (r & 7)) << 4));
            size_t go = ((size_t)(m0 + r) * 512 + k0 + s * 64) * 2 + c * 16;
            *(uint4*)(sm + so) = *(const uint4*)(Ab + go);
        }
#pragma unroll
        for (int i = 0; i < 4; i++) {
            int idx = i * 256 + tid;
            int s = idx >> 9, rem = idx & 511;
            int r = rem >> 3, c = rem & 7;
            uint32_t so = (uint32_t)(32768 + s * 8192 + r * 128 + ((c ^ (r & 7)) << 4));
            size_t go = ((size_t)(n0 + r) * 512 + k0 + s * 64) * 2 + c * 16;
            *(uint4*)(sm + so) = *(const uint4*)(Bb + go);
        }
        __syncthreads();

#pragma unroll
        for (int sub = 0; sub < 2; sub++) {
            const uint32_t sA = sbase + sub * 16384;
            const uint32_t sB = sbase + 32768 + sub * 8192;
#pragma unroll
            for (int ks = 0; ks < 4; ks++) {
                uint32_t a[8], b[8];
                int cA = ks * 2 + khA;
                uint32_t aoff = (uint32_t)(rA * 128 + ((cA ^ swA) << 4));
                int cB = ks * 2 + khB;
                uint32_t boff = (uint32_t)(rB * 128 + ((cB ^ swB) << 4));

                ldsm4(a + 0, sA + aoff);
                ldsm4(a + 4, sA + aoff + 2048);
                ldsm4(b + 0, sB + boff);
                ldsm4(b + 4, sB + boff + 2048);
#pragma unroll
                for (int mt = 0; mt < 2; mt++)
#pragma unroll
                    for (int nt = 0; nt < 4; nt++)
                        mma16816(acc[mt][nt], a + 4 * mt, b + nt * 2);
            }
        }
        __syncthreads();
    }

    const int g = lane >> 2, t4 = lane & 3;
#pragma unroll
    for (int mt = 0; mt < 2; mt++) {
#pragma unroll
        for (int nt = 0; nt < 4; nt++) {
            int row = m0 + wm * 32 + mt * 16 + g;
            int col = n0 + wn * 32 + nt * 8 + t4 * 2;
            float b0 = bias[col], b1 = bias[col + 1];
            float f0 = acc[mt][nt][0] + b0;
            float f1 = acc[mt][nt][1] + b1;
            float f2 = acc[mt][nt][2] + b0;
            float f3 = acc[mt][nt][3] + b1;
            if (act) {
                f0 = (f0 > 0.f) ? (f0 + 1.f) : __expf(f0);
                f1 = (f1 > 0.f) ? (f1 + 1.f) : __expf(f1);
                f2 = (f2 > 0.f) ? (f2 + 1.f) : __expf(f2);
                f3 = (f3 > 0.f) ? (f3 + 1.f) : __expf(f3);
            }
            if (C16) {
                *(__half2*)(C16 + (size_t)row * 512 + col)       = __floats2half2_rn(f0, f1);
                *(__half2*)(C16 + (size_t)(row + 8) * 512 + col) = __floats2half2_rn(f2, f3);
            } else {
                *(float2*)(C32 + (size_t)row * 512 + col)       = make_float2(f0, f1);
                *(float2*)(C32 + (size_t)(row + 8) * 512 + col) = make_float2(f2, f3);
            }
        }
    }
}

// grid (256, 8, 3): z = matrix (0=Q,1=K,2=V), y = n-tile of 64. fp16 out.
__global__ __launch_bounds__(256, 2) void qkv_mma(const float* __restrict__ bq,
                                                  const float* __restrict__ bk,
                                                  const float* __restrict__ bv)
{
    int mat = blockIdx.z;
    const __half* Bm = g_w16 + (size_t)mat * 262144;
    const float* bias = (mat == 0) ? bq : (mat == 1) ? bk : bv;
    __half* C = (mat == 0) ? g_q16 : (mat == 1) ? g_k16 : g_v16;
    gemm_mma_body(g_x16, Bm, bias, nullptr, C, mat < 2, blockIdx.x * 128, blockIdx.y * 64);
}

// grid (256, 8). fp32 out.
__global__ __launch_bounds__(256, 2) void out_mma(float* __restrict__ out,
                                                  const float* __restrict__ bo)
{
    gemm_mma_body(g_a16, g_w16 + (size_t)3 * 262144, bo, out, nullptr, false,
                  blockIdx.x * 128, blockIdx.y * 64);
}

// ============================================================
// x -> fp16
__global__ __launch_bounds__(256) void split_x(const float* __restrict__ x)
{
    size_t i4 = ((size_t)blockIdx.x * 256 + threadIdx.x) * 4;
    float4 v = *(const float4*)(x + i4);
    *(__half2*)(g_x16 + i4)     = __floats2half2_rn(v.x, v.y);
    *(__half2*)(g_x16 + i4 + 2) = __floats2half2_rn(v.z, v.w);
}

// transpose weights: W [k][n] fp32 -> Wt [n][k] fp16. grid(16,16,4) block(32,8)
__global__ __launch_bounds__(256) void tsplit_w(const float* __restrict__ Wq,
                                                const float* __restrict__ Wk,
                                                const float* __restrict__ Wv,
                                                const float* __restrict__ Wo)
{
    const float* W = (blockIdx.z == 0) ? Wq : (blockIdx.z == 1) ? Wk
                   : (blockIdx.z == 2) ? Wv : Wo;
    __half* oh = g_w16 + (size_t)blockIdx.z * 262144;
    __shared__ float t[32][33];
    int nx = blockIdx.x * 32 + threadIdx.x;
    int k0 = blockIdx.y * 32;
#pragma unroll
    for (int j = 0; j < 4; j++)
        t[threadIdx.y + j * 8][threadIdx.x] = W[(size_t)(k0 + threadIdx.y + j * 8) * 512 + nx];
    __syncthreads();
#pragma unroll
    for (int j = 0; j < 4; j++) {
        int nr = blockIdx.x * 32 + threadIdx.y + j * 8;
        int kc = k0 + threadIdx.x;
        oh[(size_t)nr * 512 + kc] = __float2half(t[threadIdx.x][threadIdx.y + j * 8]);
    }
}

// ============================================================
// KV state via tensor cores (R9 proven): partial kv[d][m] = sum_s k[s,d]*v[s,m].
__global__ __launch_bounds__(256) void kv_mma()
{
    const int bh = blockIdx.y;
    const int b = bh >> 3, h = bh & 7;
    const int tid = threadIdx.x;
    const int wid = tid >> 5, lane = tid & 31;
    const int sub = wid >> 1, nh = wid & 1;

    __shared__ __align__(1024) __half sK[128 * 64];
    __shared__ __align__(1024) __half sV[128 * 64];
    const uint32_t kb = smem_u32(sK), vb = smem_u32(sV);

    float acc[4][4][4];
#pragma unroll
    for (int i = 0; i < 4; i++)
#pragma unroll
        for (int j = 0; j < 4; j++)
#pragma unroll
            for (int t = 0; t < 4; t++) acc[i][j][t] = 0.f;

    const char* gk = (const char*)g_k16 + ((size_t)(b * S_ + blockIdx.x * 1024)) * 1024 + h * 128;
    const char* gv = (const char*)g_v16 + ((size_t)(b * S_ + blockIdx.x * 1024)) * 1024 + h * 128;

    const int rAl = ((lane >> 4) & 1) * 8 + (lane & 7);
    const int cA16 = (lane >> 3) & 1;
    const int rBl = ((lane >> 3) & 1) * 8 + (lane & 7);
    const int cB16 = (lane >> 4) & 1;

    for (int t = 0; t < 8; t++) {
#pragma unroll
        for (int i = 0; i < 4; i++) {
            int idx = i * 256 + tid;
            int r = idx >> 3, c = idx & 7;
            uint32_t so = (uint32_t)(r * 128 + ((c ^ (r & 7)) << 4));
            size_t go = (size_t)(t * 128 + r) * 1024 + c * 16;
            *(uint4*)((char*)sK + so) = *(const uint4*)(gk + go);
            *(uint4*)((char*)sV + so) = *(const uint4*)(gv + go);
        }
        __syncthreads();

#pragma unroll
        for (int kst = 0; kst < 2; kst++) {
            int s0 = sub * 32 + kst * 16;
            uint32_t a[4][4], bf[2][4];
#pragma unroll
            for (int mt = 0; mt < 4; mt++) {
                int r = s0 + rAl;
                int c = mt * 2 + cA16;
                ldsm4t(a[mt], kb + (uint32_t)(r * 128 + ((c ^ (r & 7)) << 4)));
            }
#pragma unroll
            for (int p = 0; p < 2; p++) {
                int r = s0 + rBl;
                int c = nh * 4 + p * 2 + cB16;
                ldsm4t(bf[p], vb + (uint32_t)(r * 128 + ((c ^ (r & 7)) << 4)));
            }
#pragma unroll
            for (int mt = 0; mt < 4; mt++)
#pragma unroll
                for (int nt = 0; nt < 4; nt++)
                    mma16816(acc[mt][nt], a[mt], &bf[nt >> 1][(nt & 1) * 2]);
        }
        __syncthreads();
    }

    float* ob = g_kvp + ((size_t)bh * 16 + blockIdx.x * 4 + sub) * 4096 + nh * 32;
    const int g = lane >> 2, t4 = lane & 3;
#pragma unroll
    for (int mt = 0; mt < 4; mt++) {
#pragma unroll
        for (int nt = 0; nt < 4; nt++) {
            int d = mt * 16 + g, col = nt * 8 + t4 * 2;
            *(float2*)(ob + (size_t)d * 64 + col)       = make_float2(acc[mt][nt][0], acc[mt][nt][1]);
            *(float2*)(ob + (size_t)(d + 8) * 64 + col) = make_float2(acc[mt][nt][2], acc[mt][nt][3]);
        }
    }
}

// ksum partials from fp16 k: grid (64, 4), block 256
__global__ __launch_bounds__(256) void ksum_part()
{
    const int bh = blockIdx.x;
    const int grp = blockIdx.y;
    const int b = bh >> 3, h = bh & 7;
    const int tid = threadIdx.x;
    const int d = tid & 63, sg = tid >> 6;

    float s = 0.f;
    const __half* kp = g_k16 + ((size_t)b * S_) * 512 + h * 64 + d;
#pragma unroll 4
    for (int s0 = grp * 1024 + sg; s0 < (grp + 1) * 1024; s0 += 4)
        s += __half2float(kp[(size_t)s0 * 512]);

    __shared__ float red[256];
    red[tid] = s;
    __syncthreads();
    if (sg == 0)
        g_ksp[(bh * 4 + grp) * 64 + d] = red[d] + red[64 + d] + red[128 + d] + red[192 + d];
}

// reduce partials -> KV^T fp16 hi/lo [bh][80][64]: rows 0-63 kv^T (row m, col d),
// row 64 = ksum, rows 65-79 zero. grid 64, block 256.
__global__ __launch_bounds__(256) void kv_reduce()
{
    const int bh = blockIdx.x;
    const int tid = threadIdx.x;
    for (int idx = tid; idx < 4096; idx += 256) {
        float s = 0.f;
#pragma unroll
        for (int c = 0; c < 16; c++)
            s += g_kvp[((size_t)bh * 16 + c) * 4096 + idx];
        int d = idx >> 6, m = idx & 63;
        __half hi = __float2half(s);
        size_t o = ((size_t)bh * 80 + m) * 64 + d;
        g_kvth[o] = hi;
        g_kvtl[o] = __float2half(s - __half2float(hi));
    }
    if (tid < 64) {
        float s = g_ksp[(bh * 4 + 0) * 64 + tid] + g_ksp[(bh * 4 + 1) * 64 + tid]
                + g_ksp[(bh * 4 + 2) * 64 + tid] + g_ksp[(bh * 4 + 3) * 64 + tid];
        __half hi = __float2half(s);
        size_t o = ((size_t)bh * 80 + 64) * 64 + tid;
        g_kvth[o] = hi;
        g_kvtl[o] = __float2half(s - __half2float(hi));
    }
    for (int idx = tid; idx < 15 * 64; idx += 256) {
        size_t o = ((size_t)bh * 80 + 65) * 64 + idx;
        g_kvth[o] = __float2half(0.f);
        g_kvtl[o] = __float2half(0.f);
    }
}

// ============================================================
// Attention readout via HMMA: per (bh, 128-row tile),
// C[128, 80] = q_tile @ (KVT_hi + KVT_lo)^T ; col 64 = denominator.
// grid (32, 64), block 256 = 8 warps x 16 rows.
__global__ __launch_bounds__(256) void attn_mma()
{
    const int bh = blockIdx.y;
    const int b = bh >> 3, h = bh & 7;
    const int l0 = blockIdx.x * 128;
    const int tid = threadIdx.x;
    const int wid = tid >> 5, lane = tid & 31;

    __shared__ __align__(1024) __half sQ[128 * 64];
    __shared__ __align__(1024) __half sB[2][80 * 64];
    __shared__ float sDen[128];

    // load q tile: 128 rows x 128B = 1024 chunks
#pragma unroll
    for (int i = 0; i < 4; i++) {
        int idx = i * 256 + tid;
        int r = idx >> 3, c = idx & 7;
        uint32_t so = (uint32_t)(r * 128 + ((c ^ (r & 7)) << 4));
        size_t go = (((size_t)(b * S_ + l0 + r)) * 512 + h * 64) * 2 + c * 16;
        *(uint4*)((char*)sQ + so) = *(const uint4*)((const char*)g_q16 + go);
    }
    // load KVT hi/lo: 2 x 80 rows x 128B = 1280 chunks
#pragma unroll
    for (int i = 0; i < 5; i++) {
        int idx = i * 256 + tid;
        int r = idx >> 3, c = idx & 7;   // r in 0..159
        int arr = r >= 80;
        int rr = arr ? r - 80 : r;
        uint32_t so = (uint32_t)(rr * 128 + ((c ^ (rr & 7)) << 4));
        size_t go = (((size_t)bh * 80 + rr) * 64) * 2 + c * 16;
        const char* src = arr ? (const char*)g_kvtl : (const char*)g_kvth;
        *(uint4*)((char*)sB[arr] + so) = *(const uint4*)(src + go);
    }
    __syncthreads();

    const uint32_t qb = smem_u32(sQ);
    const uint32_t bb0 = smem_u32(sB[0]);
    const uint32_t bb1 = smem_u32(sB[1]);

    const int rA  = wid * 16 + (lane & 15);
    const int khA = (lane >> 4) & 1;
    const int swA = rA & 7;
    const int rBl = (lane & 7) + ((lane >> 1) & 8);
    const int khB = (lane >> 3) & 1;

    float acc[10][4];
#pragma unroll
    for (int n = 0; n < 10; n++)
#pragma unroll
        for (int t = 0; t < 4; t++) acc[n][t] = 0.f;

#pragma unroll
    for (int ks = 0; ks < 4; ks++) {
        uint32_t a[4];
        int cA = ks * 2 + khA;
        ldsm4(a, qb + (uint32_t)(rA * 128 + ((cA ^ swA) << 4)));
#pragma unroll
        for (int arr = 0; arr < 2; arr++) {
            uint32_t base = arr ? bb1 : bb0;
#pragma unroll
            for (int p = 0; p < 5; p++) {
                uint32_t bf[4];
                int rB = p * 16 + rBl;
                int cB = ks * 2 + khB;
                ldsm4(bf, base + (uint32_t)(rB * 128 + ((cB ^ (rB & 7)) << 4)));
                mma16816(acc[p * 2], a, bf + 0);
                if (p < 4) mma16816(acc[p * 2 + 1], a, bf + 2);
            }
        }
    }

    const int g = lane >> 2, t4 = lane & 3;
    if (t4 == 0) {
        sDen[wid * 16 + g]     = acc[8][0];
        sDen[wid * 16 + g + 8] = acc[8][2];
    }
    __syncthreads();

    int row0 = wid * 16 + g;
    float z0 = 1.0f / (sDen[row0] + EPS_);
    float z1 = 1.0f / (sDen[row0 + 8] + EPS_);
    __half* o0 = g_a16 + ((size_t)(b * S_ + l0 + row0)) * 512 + h * 64;
    __half* o1 = o0 + (size_t)8 * 512;
#pragma unroll
    for (int nt = 0; nt < 8; nt++) {
        int col = nt * 8 + t4 * 2;
        *(__half2*)(o0 + col) = __floats2half2_rn(acc[nt][0] * z0, acc[nt][1] * z0);
        *(__half2*)(o1 + col) = __floats2half2_rn(acc[nt][2] * z1, acc[nt][3] * z1);
    }
}

// ============================================================
extern "C" void kernel_launch(void* const* d_in, const int* in_sizes, int n_in,
                              void* d_out, int out_size)
{
    const float* x  = (const float*)d_in[0];
    const float* Wq = (const float*)d_in[1];
    const float* bq = (const float*)d_in[2];
    const float* Wk = (const float*)d_in[3];
    const float* bk = (const float*)d_in[4];
    const float* Wv = (const float*)d_in[5];
    const float* bv = (const float*)d_in[6];
    const float* Wo = (const float*)d_in[7];
    const float* bo = (const float*)d_in[8];
    float* out = (float*)d_out;

    split_x<<<(M_ * E_) / (256 * 4), 256>>>(x);
    tsplit_w<<<dim3(16, 16, 4), dim3(32, 8)>>>(Wq, Wk, Wv, Wo);
    qkv_mma<<<dim3(M_ / 128, 8, 3), 256>>>(bq, bk, bv);
    kv_mma<<<dim3(4, 64), 256>>>();
    ksum_part<<<dim3(64, 4), 256>>>();
    kv_reduce<<<64, 256>>>();
    attn_mma<<<dim3(32, 64), 256>>>();
    out_mma<<<dim3(M_ / 128, 8), 256>>>(out, bo);
}

// round 12
// speedup vs baseline: 3.6478x; 1.1205x over previous
#include <cuda_runtime.h>
#include <cuda_fp16.h>
#include <math.h>
#include <stdint.h>

#define B_   8
#define S_   4096
#define E_   512
#define H_   8
#define D_   64
#define M_   (B_ * S_)      // 32768 rows
#define EPS_ 1e-6f

// -------- scratch (device globals; no allocations allowed) --------
__device__ __align__(16) float g_kvp[(size_t)B_ * H_ * 16 * D_ * D_];  // [bh][16][d][m]
__device__ __align__(16) float g_ksp[B_ * H_ * 4 * D_];                // [bh][4][d]
// KV^T per head, fp16 hi/lo, [bh][80][64]; row 64 = ksum, rows 65-79 zero.
__device__ __align__(16) __half g_kvth[64 * 80 * 64];
__device__ __align__(16) __half g_kvtl[64 * 80 * 64];
// fp16 operands
__device__ __align__(16) __half g_x16[(size_t)M_ * E_];
__device__ __align__(16) __half g_q16[(size_t)M_ * E_];
__device__ __align__(16) __half g_k16[(size_t)M_ * E_];
__device__ __align__(16) __half g_v16[(size_t)M_ * E_];
__device__ __align__(16) __half g_a16[(size_t)M_ * E_];
__device__ __align__(16) __half g_w16[4 * 512 * 512];   // transposed [n][k]

// ================= portable PTX helpers =================
static __device__ __forceinline__ uint32_t smem_u32(const void* p) {
    uint32_t a;
    asm("{ .reg .u64 t; cvta.to.shared.u64 t, %1; cvt.u32.u64 %0, t; }" : "=r"(a) : "l"(p));
    return a;
}
static __device__ __forceinline__ void ldsm4(uint32_t* r, uint32_t addr) {
    asm volatile("ldmatrix.sync.aligned.m8n8.x4.shared.b16 {%0,%1,%2,%3}, [%4];"
                 : "=r"(r[0]), "=r"(r[1]), "=r"(r[2]), "=r"(r[3]) : "r"(addr));
}
static __device__ __forceinline__ void ldsm4t(uint32_t* r, uint32_t addr) {
    asm volatile("ldmatrix.sync.aligned.m8n8.x4.trans.shared.b16 {%0,%1,%2,%3}, [%4];"
                 : "=r"(r[0]), "=r"(r[1]), "=r"(r[2]), "=r"(r[3]) : "r"(addr));
}
static __device__ __forceinline__ void mma16816(float* c, const uint32_t* a, const uint32_t* b) {
    asm volatile("mma.sync.aligned.m16n8k16.row.col.f32.f16.f16.f32 "
                 "{%0,%1,%2,%3}, {%4,%5,%6,%7}, {%8,%9}, {%0,%1,%2,%3};"
                 : "+f"(c[0]), "+f"(c[1]), "+f"(c[2]), "+f"(c[3])
                 : "r"(a[0]), "r"(a[1]), "r"(a[2]), "r"(a[3]), "r"(b[0]), "r"(b[1]));
}

// ============================================================
// HMMA fp16 GEMM, BM=128 BN=128 BK=64: C[m0:+128, n0:+128] = act(A @ B^T + bias)
// 256 threads = 8 warps (4m x 2n), warp tile 32x64.
// SMEM 32KB: A(16K) | B(16K), XOR-swizzled 16B chunks.
// ============================================================
static __device__ __forceinline__ void gemm_mma_body(
    const __half* __restrict__ A, const __half* __restrict__ Bm,
    const float* __restrict__ bias, float* __restrict__ C32,
    __half* __restrict__ C16, bool act, int m0, int n0)
{
    __shared__ __align__(1024) uint8_t sm[32768];
    const int tid = threadIdx.x;
    const int wid = tid >> 5, lane = tid & 31;
    const int wm = wid & 3;          // 0..3 -> 32-row m group
    const int wn = wid >> 2;         // 0..1 -> 64-col n group
    const uint32_t sbase = smem_u32(sm);
    const uint32_t sA = sbase, sB = sbase + 16384;

    float acc[2][8][4];
#pragma unroll
    for (int i = 0; i < 2; i++)
#pragma unroll
        for (int j = 0; j < 8; j++)
#pragma unroll
            for (int t = 0; t < 4; t++) acc[i][j][t] = 0.f;

    const int rA  = wm * 32 + (lane & 15);
    const int khA = (lane >> 4) & 1;
    const int swA = rA & 7;
    const int rBl = wn * 64 + (lane & 7) + ((lane >> 1) & 8);
    const int khB = (lane >> 3) & 1;

    const char* Ab = (const char*)A;
    const char* Bb = (const char*)Bm;

    for (int kb = 0; kb < 8; kb++) {
        const int k0 = kb * 64;
        // A tile: 128 rows x 128B = 1024 chunks
#pragma unroll
        for (int i = 0; i < 4; i++) {
            int idx = i * 256 + tid;
            int r = idx >> 3, c = idx & 7;
            uint32_t so = (uint32_t)(r * 128 + ((c ^ (r & 7)) << 4));
            size_t go = ((size_t)(m0 + r) * 512 + k0) * 2 + c * 16;
            *(uint4*)(sm + so) = *(const uint4*)(Ab + go);
        }
        // B tile: 128 n-rows x 128B = 1024 chunks
#pragma unroll
        for (int i = 0; i < 4; i++) {
            int idx = i * 256 + tid;
            int r = idx >> 3, c = idx & 7;
            uint32_t so = (uint32_t)(16384 + r * 128 + ((c ^ (r & 7)) << 4));
            size_t go = ((size_t)(n0 + r) * 512 + k0) * 2 + c * 16;
            *(uint4*)(sm + so) = *(const uint4*)(Bb + go);
        }
        __syncthreads();

#pragma unroll
        for (int ks = 0; ks < 4; ks++) {
            uint32_t a[8], bf[16];
            int cA = ks * 2 + khA;
            uint32_t aoff = (uint32_t)(rA * 128 + ((cA ^ swA) << 4));
            ldsm4(a + 0, sA + aoff);
            ldsm4(a + 4, sA + aoff + 2048);
#pragma unroll
            for (int p = 0; p < 4; p++) {
                int rB = rBl + p * 16;
                int cB = ks * 2 + khB;
                ldsm4(bf + 4 * p, sB + (uint32_t)(rB * 128 + ((cB ^ (rB & 7)) << 4)));
            }
#pragma unroll
            for (int mt = 0; mt < 2; mt++)
#pragma unroll
                for (int nt = 0; nt < 8; nt++)
                    mma16816(acc[mt][nt], a + 4 * mt, bf + nt * 2);
        }
        __syncthreads();
    }

    const int g = lane >> 2, t4 = lane & 3;
#pragma unroll
    for (int mt = 0; mt < 2; mt++) {
#pragma unroll
        for (int nt = 0; nt < 8; nt++) {
            int row = m0 + wm * 32 + mt * 16 + g;
            int col = n0 + wn * 64 + nt * 8 + t4 * 2;
            float b0 = bias[col], b1 = bias[col + 1];
            float f0 = acc[mt][nt][0] + b0;
            float f1 = acc[mt][nt][1] + b1;
            float f2 = acc[mt][nt][2] + b0;
            float f3 = acc[mt][nt][3] + b1;
            if (act) {
                f0 = (f0 > 0.f) ? (f0 + 1.f) : __expf(f0);
                f1 = (f1 > 0.f) ? (f1 + 1.f) : __expf(f1);
                f2 = (f2 > 0.f) ? (f2 + 1.f) : __expf(f2);
                f3 = (f3 > 0.f) ? (f3 + 1.f) : __expf(f3);
            }
            if (C16) {
                *(__half2*)(C16 + (size_t)row * 512 + col)       = __floats2half2_rn(f0, f1);
                *(__half2*)(C16 + (size_t)(row + 8) * 512 + col) = __floats2half2_rn(f2, f3);
            } else {
                *(float2*)(C32 + (size_t)row * 512 + col)       = make_float2(f0, f1);
                *(float2*)(C32 + (size_t)(row + 8) * 512 + col) = make_float2(f2, f3);
            }
        }
    }
}

// grid (256, 4, 3): z = matrix (0=Q,1=K,2=V), y = n-tile of 128. fp16 out.
__global__ __launch_bounds__(256, 2) void qkv_mma(const float* __restrict__ bq,
                                                  const float* __restrict__ bk,
                                                  const float* __restrict__ bv)
{
    int mat = blockIdx.z;
    const __half* Bm = g_w16 + (size_t)mat * 262144;
    const float* bias = (mat == 0) ? bq : (mat == 1) ? bk : bv;
    __half* C = (mat == 0) ? g_q16 : (mat == 1) ? g_k16 : g_v16;
    gemm_mma_body(g_x16, Bm, bias, nullptr, C, mat < 2, blockIdx.x * 128, blockIdx.y * 128);
}

// grid (256, 4). fp32 out.
__global__ __launch_bounds__(256, 2) void out_mma(float* __restrict__ out,
                                                  const float* __restrict__ bo)
{
    gemm_mma_body(g_a16, g_w16 + (size_t)3 * 262144, bo, out, nullptr, false,
                  blockIdx.x * 128, blockIdx.y * 128);
}

// ============================================================
// x -> fp16
__global__ __launch_bounds__(256) void split_x(const float* __restrict__ x)
{
    size_t i4 = ((size_t)blockIdx.x * 256 + threadIdx.x) * 4;
    float4 v = *(const float4*)(x + i4);
    *(__half2*)(g_x16 + i4)     = __floats2half2_rn(v.x, v.y);
    *(__half2*)(g_x16 + i4 + 2) = __floats2half2_rn(v.z, v.w);
}

// transpose weights: W [k][n] fp32 -> Wt [n][k] fp16. grid(16,16,4) block(32,8)
__global__ __launch_bounds__(256) void tsplit_w(const float* __restrict__ Wq,
                                                const float* __restrict__ Wk,
                                                const float* __restrict__ Wv,
                                                const float* __restrict__ Wo)
{
    const float* W = (blockIdx.z == 0) ? Wq : (blockIdx.z == 1) ? Wk
                   : (blockIdx.z == 2) ? Wv : Wo;
    __half* oh = g_w16 + (size_t)blockIdx.z * 262144;
    __shared__ float t[32][33];
    int nx = blockIdx.x * 32 + threadIdx.x;
    int k0 = blockIdx.y * 32;
#pragma unroll
    for (int j = 0; j < 4; j++)
        t[threadIdx.y + j * 8][threadIdx.x] = W[(size_t)(k0 + threadIdx.y + j * 8) * 512 + nx];
    __syncthreads();
#pragma unroll
    for (int j = 0; j < 4; j++) {
        int nr = blockIdx.x * 32 + threadIdx.y + j * 8;
        int kc = k0 + threadIdx.x;
        oh[(size_t)nr * 512 + kc] = __float2half(t[threadIdx.x][threadIdx.y + j * 8]);
    }
}

// ============================================================
// KV state via tensor cores (R9 proven): partial kv[d][m] = sum_s k[s,d]*v[s,m].
__global__ __launch_bounds__(256) void kv_mma()
{
    const int bh = blockIdx.y;
    const int b = bh >> 3, h = bh & 7;
    const int tid = threadIdx.x;
    const int wid = tid >> 5, lane = tid & 31;
    const int sub = wid >> 1, nh = wid & 1;

    __shared__ __align__(1024) __half sK[128 * 64];
    __shared__ __align__(1024) __half sV[128 * 64];
    const uint32_t kb = smem_u32(sK), vb = smem_u32(sV);

    float acc[4][4][4];
#pragma unroll
    for (int i = 0; i < 4; i++)
#pragma unroll
        for (int j = 0; j < 4; j++)
#pragma unroll
            for (int t = 0; t < 4; t++) acc[i][j][t] = 0.f;

    const char* gk = (const char*)g_k16 + ((size_t)(b * S_ + blockIdx.x * 1024)) * 1024 + h * 128;
    const char* gv = (const char*)g_v16 + ((size_t)(b * S_ + blockIdx.x * 1024)) * 1024 + h * 128;

    const int rAl = ((lane >> 4) & 1) * 8 + (lane & 7);
    const int cA16 = (lane >> 3) & 1;
    const int rBl = ((lane >> 3) & 1) * 8 + (lane & 7);
    const int cB16 = (lane >> 4) & 1;

    for (int t = 0; t < 8; t++) {
#pragma unroll
        for (int i = 0; i < 4; i++) {
            int idx = i * 256 + tid;
            int r = idx >> 3, c = idx & 7;
            uint32_t so = (uint32_t)(r * 128 + ((c ^ (r & 7)) << 4));
            size_t go = (size_t)(t * 128 + r) * 1024 + c * 16;
            *(uint4*)((char*)sK + so) = *(const uint4*)(gk + go);
            *(uint4*)((char*)sV + so) = *(const uint4*)(gv + go);
        }
        __syncthreads();

#pragma unroll
        for (int kst = 0; kst < 2; kst++) {
            int s0 = sub * 32 + kst * 16;
            uint32_t a[4][4], bf[2][4];
#pragma unroll
            for (int mt = 0; mt < 4; mt++) {
                int r = s0 + rAl;
                int c = mt * 2 + cA16;
                ldsm4t(a[mt], kb + (uint32_t)(r * 128 + ((c ^ (r & 7)) << 4)));
            }
#pragma unroll
            for (int p = 0; p < 2; p++) {
                int r = s0 + rBl;
                int c = nh * 4 + p * 2 + cB16;
                ldsm4t(bf[p], vb + (uint32_t)(r * 128 + ((c ^ (r & 7)) << 4)));
            }
#pragma unroll
            for (int mt = 0; mt < 4; mt++)
#pragma unroll
                for (int nt = 0; nt < 4; nt++)
                    mma16816(acc[mt][nt], a[mt], &bf[nt >> 1][(nt & 1) * 2]);
        }
        __syncthreads();
    }

    float* ob = g_kvp + ((size_t)bh * 16 + blockIdx.x * 4 + sub) * 4096 + nh * 32;
    const int g = lane >> 2, t4 = lane & 3;
#pragma unroll
    for (int mt = 0; mt < 4; mt++) {
#pragma unroll
        for (int nt = 0; nt < 4; nt++) {
            int d = mt * 16 + g, col = nt * 8 + t4 * 2;
            *(float2*)(ob + (size_t)d * 64 + col)       = make_float2(acc[mt][nt][0], acc[mt][nt][1]);
            *(float2*)(ob + (size_t)(d + 8) * 64 + col) = make_float2(acc[mt][nt][2], acc[mt][nt][3]);
        }
    }
}

// ksum partials from fp16 k: grid (64, 4), block 256
__global__ __launch_bounds__(256) void ksum_part()
{
    const int bh = blockIdx.x;
    const int grp = blockIdx.y;
    const int b = bh >> 3, h = bh & 7;
    const int tid = threadIdx.x;
    const int d = tid & 63, sg = tid >> 6;

    float s = 0.f;
    const __half* kp = g_k16 + ((size_t)b * S_) * 512 + h * 64 + d;
#pragma unroll 4
    for (int s0 = grp * 1024 + sg; s0 < (grp + 1) * 1024; s0 += 4)
        s += __half2float(kp[(size_t)s0 * 512]);

    __shared__ float red[256];
    red[tid] = s;
    __syncthreads();
    if (sg == 0)
        g_ksp[(bh * 4 + grp) * 64 + d] = red[d] + red[64 + d] + red[128 + d] + red[192 + d];
}

// reduce partials -> KV^T fp16 hi/lo [bh][80][64]: rows 0-63 kv^T (row m, col d),
// row 64 = ksum, rows 65-79 zero. grid 64, block 256.
__global__ __launch_bounds__(256) void kv_reduce()
{
    const int bh = blockIdx.x;
    const int tid = threadIdx.x;
    for (int idx = tid; idx < 4096; idx += 256) {
        float s = 0.f;
#pragma unroll
        for (int c = 0; c < 16; c++)
            s += g_kvp[((size_t)bh * 16 + c) * 4096 + idx];
        int d = idx >> 6, m = idx & 63;
        __half hi = __float2half(s);
        size_t o = ((size_t)bh * 80 + m) * 64 + d;
        g_kvth[o] = hi;
        g_kvtl[o] = __float2half(s - __half2float(hi));
    }
    if (tid < 64) {
        float s = g_ksp[(bh * 4 + 0) * 64 + tid] + g_ksp[(bh * 4 + 1) * 64 + tid]
                + g_ksp[(bh * 4 + 2) * 64 + tid] + g_ksp[(bh * 4 + 3) * 64 + tid];
        __half hi = __float2half(s);
        size_t o = ((size_t)bh * 80 + 64) * 64 + tid;
        g_kvth[o] = hi;
        g_kvtl[o] = __float2half(s - __half2float(hi));
    }
    for (int idx = tid; idx < 15 * 64; idx += 256) {
        size_t o = ((size_t)bh * 80 + 65) * 64 + idx;
        g_kvth[o] = __float2half(0.f);
        g_kvtl[o] = __float2half(0.f);
    }
}

// ============================================================
// Attention readout via HMMA (R10 proven): per (bh, 128-row tile),
// C[128, 80] = q_tile @ (KVT_hi + KVT_lo)^T ; col 64 = denominator.
// grid (32, 64), block 256 = 8 warps x 16 rows.
__global__ __launch_bounds__(256) void attn_mma()
{
    const int bh = blockIdx.y;
    const int b = bh >> 3, h = bh & 7;
    const int l0 = blockIdx.x * 128;
    const int tid = threadIdx.x;
    const int wid = tid >> 5, lane = tid & 31;

    __shared__ __align__(1024) __half sQ[128 * 64];
    __shared__ __align__(1024) __half sB[2][80 * 64];
    __shared__ float sDen[128];

#pragma unroll
    for (int i = 0; i < 4; i++) {
        int idx = i * 256 + tid;
        int r = idx >> 3, c = idx & 7;
        uint32_t so = (uint32_t)(r * 128 + ((c ^ (r & 7)) << 4));
        size_t go = (((size_t)(b * S_ + l0 + r)) * 512 + h * 64) * 2 + c * 16;
        *(uint4*)((char*)sQ + so) = *(const uint4*)((const char*)g_q16 + go);
    }
#pragma unroll
    for (int i = 0; i < 5; i++) {
        int idx = i * 256 + tid;
        int r = idx >> 3, c = idx & 7;   // r in 0..159
        int arr = r >= 80;
        int rr = arr ? r - 80 : r;
        uint32_t so = (uint32_t)(rr * 128 + ((c ^ (rr & 7)) << 4));
        size_t go = (((size_t)bh * 80 + rr) * 64) * 2 + c * 16;
        const char* src = arr ? (const char*)g_kvtl : (const char*)g_kvth;
        *(uint4*)((char*)sB[arr] + so) = *(const uint4*)(src + go);
    }
    __syncthreads();

    const uint32_t qb = smem_u32(sQ);
    const uint32_t bb0 = smem_u32(sB[0]);
    const uint32_t bb1 = smem_u32(sB[1]);

    const int rA  = wid * 16 + (lane & 15);
    const int khA = (lane >> 4) & 1;
    const int swA = rA & 7;
    const int rBl = (lane & 7) + ((lane >> 1) & 8);
    const int khB = (lane >> 3) & 1;

    float acc[10][4];
#pragma unroll
    for (int n = 0; n < 10; n++)
#pragma unroll
        for (int t = 0; t < 4; t++) acc[n][t] = 0.f;

#pragma unroll
    for (int ks = 0; ks < 4; ks++) {
        uint32_t a[4];
        int cA = ks * 2 + khA;
        ldsm4(a, qb + (uint32_t)(rA * 128 + ((cA ^ swA) << 4)));
#pragma unroll
        for (int arr = 0; arr < 2; arr++) {
            uint32_t base = arr ? bb1 : bb0;
#pragma unroll
            for (int p = 0; p < 5; p++) {
                uint32_t bf[4];
                int rB = p * 16 + rBl;
                int cB = ks * 2 + khB;
                ldsm4(bf, base + (uint32_t)(rB * 128 + ((cB ^ (rB & 7)) << 4)));
                mma16816(acc[p * 2], a, bf + 0);
                if (p < 4) mma16816(acc[p * 2 + 1], a, bf + 2);
            }
        }
    }

    const int g = lane >> 2, t4 = lane & 3;
    if (t4 == 0) {
        sDen[wid * 16 + g]     = acc[8][0];
        sDen[wid * 16 + g + 8] = acc[8][2];
    }
    __syncthreads();

    int row0 = wid * 16 + g;
    float z0 = 1.0f / (sDen[row0] + EPS_);
    float z1 = 1.0f / (sDen[row0 + 8] + EPS_);
    __half* o0 = g_a16 + ((size_t)(b * S_ + l0 + row0)) * 512 + h * 64;
    __half* o1 = o0 + (size_t)8 * 512;
#pragma unroll
    for (int nt = 0; nt < 8; nt++) {
        int col = nt * 8 + t4 * 2;
        *(__half2*)(o0 + col) = __floats2half2_rn(acc[nt][0] * z0, acc[nt][1] * z0);
        *(__half2*)(o1 + col) = __floats2half2_rn(acc[nt][2] * z1, acc[nt][3] * z1);
    }
}

// ============================================================
extern "C" void kernel_launch(void* const* d_in, const int* in_sizes, int n_in,
                              void* d_out, int out_size)
{
    const float* x  = (const float*)d_in[0];
    const float* Wq = (const float*)d_in[1];
    const float* bq = (const float*)d_in[2];
    const float* Wk = (const float*)d_in[3];
    const float* bk = (const float*)d_in[4];
    const float* Wv = (const float*)d_in[5];
    const float* bv = (const float*)d_in[6];
    const float* Wo = (const float*)d_in[7];
    const float* bo = (const float*)d_in[8];
    float* out = (float*)d_out;

    split_x<<<(M_ * E_) / (256 * 4), 256>>>(x);
    tsplit_w<<<dim3(16, 16, 4), dim3(32, 8)>>>(Wq, Wk, Wv, Wo);
    qkv_mma<<<dim3(M_ / 128, 4, 3), 256>>>(bq, bk, bv);
    kv_mma<<<dim3(4, 64), 256>>>();
    ksum_part<<<dim3(64, 4), 256>>>();
    kv_reduce<<<64, 256>>>();
    attn_mma<<<dim3(32, 64), 256>>>();
    out_mma<<<dim3(M_ / 128, 4), 256>>>(out, bo);
}

// round 13
// speedup vs baseline: 3.8931x; 1.0672x over previous
#include <cuda_runtime.h>
#include <cuda_fp16.h>
#include <math.h>
#include <stdint.h>

#define B_   8
#define S_   4096
#define E_   512
#define H_   8
#define D_   64
#define M_   (B_ * S_)      // 32768 rows
#define EPS_ 1e-6f

// -------- scratch (device globals; no allocations allowed) --------
__device__ __align__(16) float g_kvp[(size_t)B_ * H_ * 16 * D_ * D_];  // [bh][16][d][m]
__device__ __align__(16) float g_ksp[B_ * H_ * 4 * D_];                // [bh][4][d]
// KV^T per head, fp16 hi/lo, [bh][80][64]; row 64 = ksum, rows 65-79 zero.
__device__ __align__(16) __half g_kvth[64 * 80 * 64];
__device__ __align__(16) __half g_kvtl[64 * 80 * 64];
// fp16 operands
__device__ __align__(16) __half g_x16[(size_t)M_ * E_];
__device__ __align__(16) __half g_q16[(size_t)M_ * E_];
__device__ __align__(16) __half g_k16[(size_t)M_ * E_];
__device__ __align__(16) __half g_v16[(size_t)M_ * E_];
__device__ __align__(16) __half g_a16[(size_t)M_ * E_];
__device__ __align__(16) __half g_w16[4 * 512 * 512];   // transposed [n][k]

// ================= portable PTX helpers =================
static __device__ __forceinline__ uint32_t smem_u32(const void* p) {
    uint32_t a;
    asm("{ .reg .u64 t; cvta.to.shared.u64 t, %1; cvt.u32.u64 %0, t; }" : "=r"(a) : "l"(p));
    return a;
}
static __device__ __forceinline__ void ldsm4(uint32_t* r, uint32_t addr) {
    asm volatile("ldmatrix.sync.aligned.m8n8.x4.shared.b16 {%0,%1,%2,%3}, [%4];"
                 : "=r"(r[0]), "=r"(r[1]), "=r"(r[2]), "=r"(r[3]) : "r"(addr));
}
static __device__ __forceinline__ void ldsm4t(uint32_t* r, uint32_t addr) {
    asm volatile("ldmatrix.sync.aligned.m8n8.x4.trans.shared.b16 {%0,%1,%2,%3}, [%4];"
                 : "=r"(r[0]), "=r"(r[1]), "=r"(r[2]), "=r"(r[3]) : "r"(addr));
}
static __device__ __forceinline__ void mma16816(float* c, const uint32_t* a, const uint32_t* b) {
    asm volatile("mma.sync.aligned.m16n8k16.row.col.f32.f16.f16.f32 "
                 "{%0,%1,%2,%3}, {%4,%5,%6,%7}, {%8,%9}, {%0,%1,%2,%3};"
                 : "+f"(c[0]), "+f"(c[1]), "+f"(c[2]), "+f"(c[3])
                 : "r"(a[0]), "r"(a[1]), "r"(a[2]), "r"(a[3]), "r"(b[0]), "r"(b[1]));
}
static __device__ __forceinline__ void cp16(uint32_t dst, const void* src) {
    asm volatile("cp.async.cg.shared.global [%0], [%1], 16;" :: "r"(dst), "l"(src));
}
static __device__ __forceinline__ void cp_commit() {
    asm volatile("cp.async.commit_group;");
}
template <int N> static __device__ __forceinline__ void cp_wait() {
    asm volatile("cp.async.wait_group %0;" :: "n"(N));
}

// ============================================================
// HMMA fp16 GEMM, BM=128 BN=256 BK=64, 512 threads (16 warps, 4m x 4n),
// warp tile 32x64, 2-stage cp.async pipeline.
// Dynamic SMEM 96KB: 2 stages x (A 16K | B 32K), XOR-swizzled 16B chunks.
// ============================================================
#define GSTAGE 49152
#define GEMM_DSMEM (2 * GSTAGE)

static __device__ __forceinline__ void gemm_issue(
    uint32_t sb, int tid, int k0, int m0, int n0,
    const char* Ab, const char* Bb)
{
#pragma unroll
    for (int i = 0; i < 2; i++) {
        int idx = i * 512 + tid;
        int r = idx >> 3, c = idx & 7;
        uint32_t so = (uint32_t)(r * 128 + ((c ^ (r & 7)) << 4));
        size_t go = ((size_t)(m0 + r) * 512 + k0) * 2 + c * 16;
        cp16(sb + so, Ab + go);
    }
#pragma unroll
    for (int i = 0; i < 4; i++) {
        int idx = i * 512 + tid;
        int r = idx >> 3, c = idx & 7;
        uint32_t so = (uint32_t)(16384 + r * 128 + ((c ^ (r & 7)) << 4));
        size_t go = ((size_t)(n0 + r) * 512 + k0) * 2 + c * 16;
        cp16(sb + so, Bb + go);
    }
    cp_commit();
}

static __device__ __forceinline__ void gemm_mma_body(
    const __half* __restrict__ A, const __half* __restrict__ Bm,
    const float* __restrict__ bias, float* __restrict__ C32,
    __half* __restrict__ C16, bool act, int m0, int n0)
{
    extern __shared__ __align__(1024) uint8_t dsm[];
    const int tid = threadIdx.x;
    const int wid = tid >> 5, lane = tid & 31;
    const int wm = wid & 3;          // 0..3 -> 32-row m group
    const int wn = wid >> 2;         // 0..3 -> 64-col n group
    const uint32_t sbase = smem_u32(dsm);

    float acc[2][8][4];
#pragma unroll
    for (int i = 0; i < 2; i++)
#pragma unroll
        for (int j = 0; j < 8; j++)
#pragma unroll
            for (int t = 0; t < 4; t++) acc[i][j][t] = 0.f;

    const int rA  = wm * 32 + (lane & 15);
    const int khA = (lane >> 4) & 1;
    const int swA = rA & 7;
    const int rBl = wn * 64 + (lane & 7) + ((lane >> 1) & 8);
    const int khB = (lane >> 3) & 1;

    const char* Ab = (const char*)A;
    const char* Bb = (const char*)Bm;

    gemm_issue(sbase, tid, 0, m0, n0, Ab, Bb);

    for (int kb = 0; kb < 8; kb++) {
        if (kb < 7) {
            gemm_issue(sbase + ((kb + 1) & 1) * GSTAGE, tid, (kb + 1) * 64, m0, n0, Ab, Bb);
            cp_wait<1>();
        } else {
            cp_wait<0>();
        }
        __syncthreads();

        const uint32_t st = sbase + (kb & 1) * GSTAGE;
        const uint32_t sA = st, sB = st + 16384;

#pragma unroll
        for (int ks = 0; ks < 4; ks++) {
            uint32_t a[8], bf[16];
            int cA = ks * 2 + khA;
            uint32_t aoff = (uint32_t)(rA * 128 + ((cA ^ swA) << 4));
            ldsm4(a + 0, sA + aoff);
            ldsm4(a + 4, sA + aoff + 2048);
#pragma unroll
            for (int p = 0; p < 4; p++) {
                int rB = rBl + p * 16;
                int cB = ks * 2 + khB;
                ldsm4(bf + 4 * p, sB + (uint32_t)(rB * 128 + ((cB ^ (rB & 7)) << 4)));
            }
#pragma unroll
            for (int mt = 0; mt < 2; mt++)
#pragma unroll
                for (int nt = 0; nt < 8; nt++)
                    mma16816(acc[mt][nt], a + 4 * mt, bf + nt * 2);
        }
        __syncthreads();
    }

    const int g = lane >> 2, t4 = lane & 3;
#pragma unroll
    for (int mt = 0; mt < 2; mt++) {
#pragma unroll
        for (int nt = 0; nt < 8; nt++) {
            int row = m0 + wm * 32 + mt * 16 + g;
            int col = n0 + wn * 64 + nt * 8 + t4 * 2;
            float b0 = bias[col], b1 = bias[col + 1];
            float f0 = acc[mt][nt][0] + b0;
            float f1 = acc[mt][nt][1] + b1;
            float f2 = acc[mt][nt][2] + b0;
            float f3 = acc[mt][nt][3] + b1;
            if (act) {
                f0 = (f0 > 0.f) ? (f0 + 1.f) : __expf(f0);
                f1 = (f1 > 0.f) ? (f1 + 1.f) : __expf(f1);
                f2 = (f2 > 0.f) ? (f2 + 1.f) : __expf(f2);
                f3 = (f3 > 0.f) ? (f3 + 1.f) : __expf(f3);
            }
            if (C16) {
                *(__half2*)(C16 + (size_t)row * 512 + col)       = __floats2half2_rn(f0, f1);
                *(__half2*)(C16 + (size_t)(row + 8) * 512 + col) = __floats2half2_rn(f2, f3);
            } else {
                *(float2*)(C32 + (size_t)row * 512 + col)       = make_float2(f0, f1);
                *(float2*)(C32 + (size_t)(row + 8) * 512 + col) = make_float2(f2, f3);
            }
        }
    }
}

// grid (256, 2, 3): z = matrix (0=Q,1=K,2=V), y = n-tile of 256. fp16 out.
__global__ __launch_bounds__(512, 1) void qkv_mma(const float* __restrict__ bq,
                                                  const float* __restrict__ bk,
                                                  const float* __restrict__ bv)
{
    int mat = blockIdx.z;
    const __half* Bm = g_w16 + (size_t)mat * 262144;
    const float* bias = (mat == 0) ? bq : (mat == 1) ? bk : bv;
    __half* C = (mat == 0) ? g_q16 : (mat == 1) ? g_k16 : g_v16;
    gemm_mma_body(g_x16, Bm, bias, nullptr, C, mat < 2, blockIdx.x * 128, blockIdx.y * 256);
}

// grid (256, 2). fp32 out.
__global__ __launch_bounds__(512, 1) void out_mma(float* __restrict__ out,
                                                  const float* __restrict__ bo)
{
    gemm_mma_body(g_a16, g_w16 + (size_t)3 * 262144, bo, out, nullptr, false,
                  blockIdx.x * 128, blockIdx.y * 256);
}

// ============================================================
// x -> fp16
__global__ __launch_bounds__(256) void split_x(const float* __restrict__ x)
{
    size_t i4 = ((size_t)blockIdx.x * 256 + threadIdx.x) * 4;
    float4 v = *(const float4*)(x + i4);
    *(__half2*)(g_x16 + i4)     = __floats2half2_rn(v.x, v.y);
    *(__half2*)(g_x16 + i4 + 2) = __floats2half2_rn(v.z, v.w);
}

// transpose weights: W [k][n] fp32 -> Wt [n][k] fp16. grid(16,16,4) block(32,8)
__global__ __launch_bounds__(256) void tsplit_w(const float* __restrict__ Wq,
                                                const float* __restrict__ Wk,
                                                const float* __restrict__ Wv,
                                                const float* __restrict__ Wo)
{
    const float* W = (blockIdx.z == 0) ? Wq : (blockIdx.z == 1) ? Wk
                   : (blockIdx.z == 2) ? Wv : Wo;
    __half* oh = g_w16 + (size_t)blockIdx.z * 262144;
    __shared__ float t[32][33];
    int nx = blockIdx.x * 32 + threadIdx.x;
    int k0 = blockIdx.y * 32;
#pragma unroll
    for (int j = 0; j < 4; j++)
        t[threadIdx.y + j * 8][threadIdx.x] = W[(size_t)(k0 + threadIdx.y + j * 8) * 512 + nx];
    __syncthreads();
#pragma unroll
    for (int j = 0; j < 4; j++) {
        int nr = blockIdx.x * 32 + threadIdx.y + j * 8;
        int kc = k0 + threadIdx.x;
        oh[(size_t)nr * 512 + kc] = __float2half(t[threadIdx.x][threadIdx.y + j * 8]);
    }
}

// ============================================================
// KV state via tensor cores (R9 proven): partial kv[d][m] = sum_s k[s,d]*v[s,m].
__global__ __launch_bounds__(256) void kv_mma()
{
    const int bh = blockIdx.y;
    const int b = bh >> 3, h = bh & 7;
    const int tid = threadIdx.x;
    const int wid = tid >> 5, lane = tid & 31;
    const int sub = wid >> 1, nh = wid & 1;

    __shared__ __align__(1024) __half sK[128 * 64];
    __shared__ __align__(1024) __half sV[128 * 64];
    const uint32_t kb = smem_u32(sK), vb = smem_u32(sV);

    float acc[4][4][4];
#pragma unroll
    for (int i = 0; i < 4; i++)
#pragma unroll
        for (int j = 0; j < 4; j++)
#pragma unroll
            for (int t = 0; t < 4; t++) acc[i][j][t] = 0.f;

    const char* gk = (const char*)g_k16 + ((size_t)(b * S_ + blockIdx.x * 1024)) * 1024 + h * 128;
    const char* gv = (const char*)g_v16 + ((size_t)(b * S_ + blockIdx.x * 1024)) * 1024 + h * 128;

    const int rAl = ((lane >> 4) & 1) * 8 + (lane & 7);
    const int cA16 = (lane >> 3) & 1;
    const int rBl = ((lane >> 3) & 1) * 8 + (lane & 7);
    const int cB16 = (lane >> 4) & 1;

    for (int t = 0; t < 8; t++) {
#pragma unroll
        for (int i = 0; i < 4; i++) {
            int idx = i * 256 + tid;
            int r = idx >> 3, c = idx & 7;
            uint32_t so = (uint32_t)(r * 128 + ((c ^ (r & 7)) << 4));
            size_t go = (size_t)(t * 128 + r) * 1024 + c * 16;
            *(uint4*)((char*)sK + so) = *(const uint4*)(gk + go);
            *(uint4*)((char*)sV + so) = *(const uint4*)(gv + go);
        }
        __syncthreads();

#pragma unroll
        for (int kst = 0; kst < 2; kst++) {
            int s0 = sub * 32 + kst * 16;
            uint32_t a[4][4], bf[2][4];
#pragma unroll
            for (int mt = 0; mt < 4; mt++) {
                int r = s0 + rAl;
                int c = mt * 2 + cA16;
                ldsm4t(a[mt], kb + (uint32_t)(r * 128 + ((c ^ (r & 7)) << 4)));
            }
#pragma unroll
            for (int p = 0; p < 2; p++) {
                int r = s0 + rBl;
                int c = nh * 4 + p * 2 + cB16;
                ldsm4t(bf[p], vb + (uint32_t)(r * 128 + ((c ^ (r & 7)) << 4)));
            }
#pragma unroll
            for (int mt = 0; mt < 4; mt++)
#pragma unroll
                for (int nt = 0; nt < 4; nt++)
                    mma16816(acc[mt][nt], a[mt], &bf[nt >> 1][(nt & 1) * 2]);
        }
        __syncthreads();
    }

    float* ob = g_kvp + ((size_t)bh * 16 + blockIdx.x * 4 + sub) * 4096 + nh * 32;
    const int g = lane >> 2, t4 = lane & 3;
#pragma unroll
    for (int mt = 0; mt < 4; mt++) {
#pragma unroll
        for (int nt = 0; nt < 4; nt++) {
            int d = mt * 16 + g, col = nt * 8 + t4 * 2;
            *(float2*)(ob + (size_t)d * 64 + col)       = make_float2(acc[mt][nt][0], acc[mt][nt][1]);
            *(float2*)(ob + (size_t)(d + 8) * 64 + col) = make_float2(acc[mt][nt][2], acc[mt][nt][3]);
        }
    }
}

// ksum partials from fp16 k: grid (64, 4), block 256
__global__ __launch_bounds__(256) void ksum_part()
{
    const int bh = blockIdx.x;
    const int grp = blockIdx.y;
    const int b = bh >> 3, h = bh & 7;
    const int tid = threadIdx.x;
    const int d = tid & 63, sg = tid >> 6;

    float s = 0.f;
    const __half* kp = g_k16 + ((size_t)b * S_) * 512 + h * 64 + d;
#pragma unroll 4
    for (int s0 = grp * 1024 + sg; s0 < (grp + 1) * 1024; s0 += 4)
        s += __half2float(kp[(size_t)s0 * 512]);

    __shared__ float red[256];
    red[tid] = s;
    __syncthreads();
    if (sg == 0)
        g_ksp[(bh * 4 + grp) * 64 + d] = red[d] + red[64 + d] + red[128 + d] + red[192 + d];
}

// reduce partials -> KV^T fp16 hi/lo [bh][80][64]: rows 0-63 kv^T (row m, col d),
// row 64 = ksum, rows 65-79 zero. grid 64, block 256.
__global__ __launch_bounds__(256) void kv_reduce()
{
    const int bh = blockIdx.x;
    const int tid = threadIdx.x;
    for (int idx = tid; idx < 4096; idx += 256) {
        float s = 0.f;
#pragma unroll
        for (int c = 0; c < 16; c++)
            s += g_kvp[((size_t)bh * 16 + c) * 4096 + idx];
        int d = idx >> 6, m = idx & 63;
        __half hi = __float2half(s);
        size_t o = ((size_t)bh * 80 + m) * 64 + d;
        g_kvth[o] = hi;
        g_kvtl[o] = __float2half(s - __half2float(hi));
    }
    if (tid < 64) {
        float s = g_ksp[(bh * 4 + 0) * 64 + tid] + g_ksp[(bh * 4 + 1) * 64 + tid]
                + g_ksp[(bh * 4 + 2) * 64 + tid] + g_ksp[(bh * 4 + 3) * 64 + tid];
        __half hi = __float2half(s);
        size_t o = ((size_t)bh * 80 + 64) * 64 + tid;
        g_kvth[o] = hi;
        g_kvtl[o] = __float2half(s - __half2float(hi));
    }
    for (int idx = tid; idx < 15 * 64; idx += 256) {
        size_t o = ((size_t)bh * 80 + 65) * 64 + idx;
        g_kvth[o] = __float2half(0.f);
        g_kvtl[o] = __float2half(0.f);
    }
}

// ============================================================
// Attention readout via HMMA (R10 proven): per (bh, 128-row tile),
// C[128, 80] = q_tile @ (KVT_hi + KVT_lo)^T ; col 64 = denominator.
// grid (32, 64), block 256 = 8 warps x 16 rows.
__global__ __launch_bounds__(256) void attn_mma()
{
    const int bh = blockIdx.y;
    const int b = bh >> 3, h = bh & 7;
    const int l0 = blockIdx.x * 128;
    const int tid = threadIdx.x;
    const int wid = tid >> 5, lane = tid & 31;

    __shared__ __align__(1024) __half sQ[128 * 64];
    __shared__ __align__(1024) __half sB[2][80 * 64];
    __shared__ float sDen[128];

#pragma unroll
    for (int i = 0; i < 4; i++) {
        int idx = i * 256 + tid;
        int r = idx >> 3, c = idx & 7;
        uint32_t so = (uint32_t)(r * 128 + ((c ^ (r & 7)) << 4));
        size_t go = (((size_t)(b * S_ + l0 + r)) * 512 + h * 64) * 2 + c * 16;
        *(uint4*)((char*)sQ + so) = *(const uint4*)((const char*)g_q16 + go);
    }
#pragma unroll
    for (int i = 0; i < 5; i++) {
        int idx = i * 256 + tid;
        int r = idx >> 3, c = idx & 7;   // r in 0..159
        int arr = r >= 80;
        int rr = arr ? r - 80 : r;
        uint32_t so = (uint32_t)(rr * 128 + ((c ^ (rr & 7)) << 4));
        size_t go = (((size_t)bh * 80 + rr) * 64) * 2 + c * 16;
        const char* src = arr ? (const char*)g_kvtl : (const char*)g_kvth;
        *(uint4*)((char*)sB[arr] + so) = *(const uint4*)(src + go);
    }
    __syncthreads();

    const uint32_t qb = smem_u32(sQ);
    const uint32_t bb0 = smem_u32(sB[0]);
    const uint32_t bb1 = smem_u32(sB[1]);

    const int rA  = wid * 16 + (lane & 15);
    const int khA = (lane >> 4) & 1;
    const int swA = rA & 7;
    const int rBl = (lane & 7) + ((lane >> 1) & 8);
    const int khB = (lane >> 3) & 1;

    float acc[10][4];
#pragma unroll
    for (int n = 0; n < 10; n++)
#pragma unroll
        for (int t = 0; t < 4; t++) acc[n][t] = 0.f;

#pragma unroll
    for (int ks = 0; ks < 4; ks++) {
        uint32_t a[4];
        int cA = ks * 2 + khA;
        ldsm4(a, qb + (uint32_t)(rA * 128 + ((cA ^ swA) << 4)));
#pragma unroll
        for (int arr = 0; arr < 2; arr++) {
            uint32_t base = arr ? bb1 : bb0;
#pragma unroll
            for (int p = 0; p < 5; p++) {
                uint32_t bf[4];
                int rB = p * 16 + rBl;
                int cB = ks * 2 + khB;
                ldsm4(bf, base + (uint32_t)(rB * 128 + ((cB ^ (rB & 7)) << 4)));
                mma16816(acc[p * 2], a, bf + 0);
                if (p < 4) mma16816(acc[p * 2 + 1], a, bf + 2);
            }
        }
    }

    const int g = lane >> 2, t4 = lane & 3;
    if (t4 == 0) {
        sDen[wid * 16 + g]     = acc[8][0];
        sDen[wid * 16 + g + 8] = acc[8][2];
    }
    __syncthreads();

    int row0 = wid * 16 + g;
    float z0 = 1.0f / (sDen[row0] + EPS_);
    float z1 = 1.0f / (sDen[row0 + 8] + EPS_);
    __half* o0 = g_a16 + ((size_t)(b * S_ + l0 + row0)) * 512 + h * 64;
    __half* o1 = o0 + (size_t)8 * 512;
#pragma unroll
    for (int nt = 0; nt < 8; nt++) {
        int col = nt * 8 + t4 * 2;
        *(__half2*)(o0 + col) = __floats2half2_rn(acc[nt][0] * z0, acc[nt][1] * z0);
        *(__half2*)(o1 + col) = __floats2half2_rn(acc[nt][2] * z1, acc[nt][3] * z1);
    }
}

// ============================================================
extern "C" void kernel_launch(void* const* d_in, const int* in_sizes, int n_in,
                              void* d_out, int out_size)
{
    const float* x  = (const float*)d_in[0];
    const float* Wq = (const float*)d_in[1];
    const float* bq = (const float*)d_in[2];
    const float* Wk = (const float*)d_in[3];
    const float* bk = (const float*)d_in[4];
    const float* Wv = (const float*)d_in[5];
    const float* bv = (const float*)d_in[6];
    const float* Wo = (const float*)d_in[7];
    const float* bo = (const float*)d_in[8];
    float* out = (float*)d_out;

    cudaFuncSetAttribute(qkv_mma, cudaFuncAttributeMaxDynamicSharedMemorySize, GEMM_DSMEM);
    cudaFuncSetAttribute(out_mma, cudaFuncAttributeMaxDynamicSharedMemorySize, GEMM_DSMEM);

    split_x<<<(M_ * E_) / (256 * 4), 256>>>(x);
    tsplit_w<<<dim3(16, 16, 4), dim3(32, 8)>>>(Wq, Wk, Wv, Wo);
    qkv_mma<<<dim3(M_ / 128, 2, 3), 512, GEMM_DSMEM>>>(bq, bk, bv);
    kv_mma<<<dim3(4, 64), 256>>>();
    ksum_part<<<dim3(64, 4), 256>>>();
    kv_reduce<<<64, 256>>>();
    attn_mma<<<dim3(32, 64), 256>>>();
    out_mma<<<dim3(M_ / 128, 2), 512, GEMM_DSMEM>>>(out, bo);
}